// round 1
// baseline (speedup 1.0000x reference)
#include <cuda_runtime.h>
#include <math.h>
#include <stdint.h>

// Problem constants (reference hardcodes these shapes)
#define NMAX 100000
#define DH   64
#define F1   128   // concat dim

// Scratch (allocation-free rule: __device__ globals)
__device__ float g_s_out[NMAX];                 // deg_out count -> rsqrt
__device__ float g_s_in [NMAX];                 // deg_in  count -> rsqrt
__device__ float g_xw1 [(size_t)NMAX * 128];    // projected gate features
__device__ float g_agg1[(size_t)NMAX * 128];    // scattered gate features
__device__ float g_xw2 [(size_t)NMAX * 64];     // projected cand features
__device__ float g_agg2[(size_t)NMAX * 64];     // scattered cand features
__device__ float g_z   [(size_t)NMAX * 64];     // update gate

// ---------------------------------------------------------------------------
// Zero accumulators + degree counters
// ---------------------------------------------------------------------------
__global__ void k_zero(int n) {
    int i = blockIdx.x * blockDim.x + threadIdx.x;
    int n32 = n * 32;            // float4 count of agg1
    int n48 = n * 48;            // + float4 count of agg2
    float4 z4 = make_float4(0.f, 0.f, 0.f, 0.f);
    if (i < n32)       ((float4*)g_agg1)[i] = z4;
    else if (i < n48)  ((float4*)g_agg2)[i - n32] = z4;
    if (i < n) { g_s_out[i] = 0.f; g_s_in[i] = 0.f; }
}

__global__ void k_degree(const int* __restrict__ src, const int* __restrict__ dst, int E) {
    int e = blockIdx.x * blockDim.x + threadIdx.x;
    if (e < E) {
        atomicAdd(&g_s_out[src[e]], 1.f);
        atomicAdd(&g_s_in [dst[e]], 1.f);
    }
}

__global__ void k_rsqrt(int n) {
    int i = blockIdx.x * blockDim.x + threadIdx.x;
    if (i < n) {
        g_s_out[i] = rsqrtf(fmaxf(g_s_out[i], 1.f));
        g_s_in [i] = rsqrtf(fmaxf(g_s_in [i], 1.f));
    }
}

// ---------------------------------------------------------------------------
// GEMM1: xw1[N,128] = diag(s_out) * [x|h] @ W_gate
// Tile: 64 rows x 128 cols, 256 threads, full W in smem.
// ---------------------------------------------------------------------------
#define G1_SMEM (128*128 + 64*129)   // floats

__global__ __launch_bounds__(256) void k_gemm1(
    const float* __restrict__ x, const float* __restrict__ h,
    const float* __restrict__ Wg, int n)
{
    extern __shared__ float sh[];
    float* Wsh = sh;               // [128][128]
    float* Ash = sh + 128 * 128;   // [64][129]
    int t = threadIdx.x;
    int row0 = blockIdx.x * 64;

    // Load W (16384 floats)
    for (int i = t; i < 128 * 128 / 4; i += 256)
        ((float4*)Wsh)[i] = ((const float4*)Wg)[i];

    // Load A tile: 64 rows x 32 float4 (x then h), scaled by s_out
    for (int i = t; i < 64 * 32; i += 256) {
        int r = i >> 5, q = i & 31;
        int gr = row0 + r;
        float4 v = make_float4(0.f, 0.f, 0.f, 0.f);
        if (gr < n) {
            float s = g_s_out[gr];
            const float4* p = (q < 16)
                ? ((const float4*)(x + (size_t)gr * 64) + q)
                : ((const float4*)(h + (size_t)gr * 64) + (q - 16));
            v = *p;
            v.x *= s; v.y *= s; v.z *= s; v.w *= s;
        }
        float* ap = Ash + r * 129 + q * 4;
        ap[0] = v.x; ap[1] = v.y; ap[2] = v.z; ap[3] = v.w;
    }
    __syncthreads();

    int tr = t >> 4;   // 0..15 -> 4 rows each
    int tc = t & 15;   // 0..15 -> 8 cols each
    float acc[4][8];
#pragma unroll
    for (int i = 0; i < 4; i++)
#pragma unroll
        for (int j = 0; j < 8; j++) acc[i][j] = 0.f;

#pragma unroll 4
    for (int k = 0; k < 128; k++) {
        float a0 = Ash[(tr * 4 + 0) * 129 + k];
        float a1 = Ash[(tr * 4 + 1) * 129 + k];
        float a2 = Ash[(tr * 4 + 2) * 129 + k];
        float a3 = Ash[(tr * 4 + 3) * 129 + k];
        float4 w0 = *(const float4*)(Wsh + k * 128 + tc * 8);
        float4 w1 = *(const float4*)(Wsh + k * 128 + tc * 8 + 4);
        float w[8] = {w0.x, w0.y, w0.z, w0.w, w1.x, w1.y, w1.z, w1.w};
#pragma unroll
        for (int j = 0; j < 8; j++) {
            acc[0][j] += a0 * w[j];
            acc[1][j] += a1 * w[j];
            acc[2][j] += a2 * w[j];
            acc[3][j] += a3 * w[j];
        }
    }

#pragma unroll
    for (int i = 0; i < 4; i++) {
        int gr = row0 + tr * 4 + i;
        if (gr < n) {
            float4* op = (float4*)(g_xw1 + (size_t)gr * 128 + tc * 8);
            op[0] = make_float4(acc[i][0], acc[i][1], acc[i][2], acc[i][3]);
            op[1] = make_float4(acc[i][4], acc[i][5], acc[i][6], acc[i][7]);
        }
    }
}

// ---------------------------------------------------------------------------
// Scatter1: agg1[dst] += xw1[src]   (one warp per edge, v4 reductions)
// ---------------------------------------------------------------------------
__global__ __launch_bounds__(256) void k_scatter1(
    const int* __restrict__ src, const int* __restrict__ dst, int E)
{
    int gt = blockIdx.x * blockDim.x + threadIdx.x;
    int e = gt >> 5;
    if (e >= E) return;
    int lane = gt & 31;
    int s = __ldg(src + e);
    int d = __ldg(dst + e);
    float4 v = __ldg((const float4*)(g_xw1 + (size_t)s * 128) + lane);
    float* p = g_agg1 + (size_t)d * 128 + lane * 4;
    asm volatile("red.global.add.v4.f32 [%0], {%1,%2,%3,%4};"
                 :: "l"(p), "f"(v.x), "f"(v.y), "f"(v.z), "f"(v.w) : "memory");
}

// ---------------------------------------------------------------------------
// Fused: gates = sigma(agg1 * s_in + b_gate) -> r,z ; build cat2 ;
//        xw2[N,64] = diag(s_out) * [x | r*h] @ W_cand ; store z
// Tile: 64 rows x 64 cols, 256 threads.
// ---------------------------------------------------------------------------
#define G2_SMEM (128*64 + 64*129)   // floats

__global__ __launch_bounds__(256) void k_gate_gemm2(
    const float* __restrict__ x, const float* __restrict__ h,
    const float* __restrict__ Wc, const float* __restrict__ bg, int n)
{
    extern __shared__ float sh[];
    float* Wsh = sh;              // [128][64]
    float* Ash = sh + 128 * 64;   // [64][129]
    int t = threadIdx.x;
    int row0 = blockIdx.x * 64;

    for (int i = t; i < 128 * 64 / 4; i += 256)
        ((float4*)Wsh)[i] = ((const float4*)Wc)[i];

    // Prologue: gates + cat2 tile
    for (int i = t; i < 64 * 64; i += 256) {
        int r = i >> 6, j = i & 63;
        int gr = row0 + r;
        float av = 0.f, bv = 0.f;
        if (gr < n) {
            float si = g_s_in[gr];
            float so = g_s_out[gr];
            float gv_r = g_agg1[(size_t)gr * 128 + j]       * si + __ldg(bg + j);
            float gv_z = g_agg1[(size_t)gr * 128 + 64 + j]  * si + __ldg(bg + 64 + j);
            float rg = 1.f / (1.f + expf(-gv_r));
            float zg = 1.f / (1.f + expf(-gv_z));
            g_z[(size_t)gr * 64 + j] = zg;
            av = so * x[(size_t)gr * 64 + j];
            bv = so * rg * h[(size_t)gr * 64 + j];
        }
        Ash[r * 129 + j]      = av;
        Ash[r * 129 + 64 + j] = bv;
    }
    __syncthreads();

    int tr = t >> 4;   // rows: 4 each
    int tc = t & 15;   // cols: 4 each
    float acc[4][4];
#pragma unroll
    for (int i = 0; i < 4; i++)
#pragma unroll
        for (int j = 0; j < 4; j++) acc[i][j] = 0.f;

#pragma unroll 4
    for (int k = 0; k < 128; k++) {
        float a0 = Ash[(tr * 4 + 0) * 129 + k];
        float a1 = Ash[(tr * 4 + 1) * 129 + k];
        float a2 = Ash[(tr * 4 + 2) * 129 + k];
        float a3 = Ash[(tr * 4 + 3) * 129 + k];
        float4 w = *(const float4*)(Wsh + k * 64 + tc * 4);
        float wv[4] = {w.x, w.y, w.z, w.w};
#pragma unroll
        for (int j = 0; j < 4; j++) {
            acc[0][j] += a0 * wv[j];
            acc[1][j] += a1 * wv[j];
            acc[2][j] += a2 * wv[j];
            acc[3][j] += a3 * wv[j];
        }
    }

#pragma unroll
    for (int i = 0; i < 4; i++) {
        int gr = row0 + tr * 4 + i;
        if (gr < n) {
            *(float4*)(g_xw2 + (size_t)gr * 64 + tc * 4) =
                make_float4(acc[i][0], acc[i][1], acc[i][2], acc[i][3]);
        }
    }
}

// ---------------------------------------------------------------------------
// Scatter2: agg2[dst] += xw2[src]   (16 threads per edge, v4 reductions)
// ---------------------------------------------------------------------------
__global__ __launch_bounds__(256) void k_scatter2(
    const int* __restrict__ src, const int* __restrict__ dst, int E)
{
    int gt = blockIdx.x * blockDim.x + threadIdx.x;
    int e = gt >> 4;
    if (e >= E) return;
    int q = gt & 15;
    int s = __ldg(src + e);
    int d = __ldg(dst + e);
    float4 v = __ldg((const float4*)(g_xw2 + (size_t)s * 64) + q);
    float* p = g_agg2 + (size_t)d * 64 + q * 4;
    asm volatile("red.global.add.v4.f32 [%0], {%1,%2,%3,%4};"
                 :: "l"(p), "f"(v.x), "f"(v.y), "f"(v.z), "f"(v.w) : "memory");
}

// ---------------------------------------------------------------------------
// Epilogue: new_h = z*h + (1-z)*tanh(agg2*s_in + b_cand)
// ---------------------------------------------------------------------------
__global__ void k_final(const float* __restrict__ h, const float* __restrict__ bc,
                        float* __restrict__ out, int n)
{
    int t = blockIdx.x * blockDim.x + threadIdx.x;
    if (t < n * 64) {
        int i = t >> 6, j = t & 63;
        float c = g_agg2[t] * g_s_in[i] + __ldg(bc + j);
        float z = g_z[t];
        out[t] = z * h[t] + (1.f - z) * tanhf(c);
    }
}

// ---------------------------------------------------------------------------
extern "C" void kernel_launch(void* const* d_in, const int* in_sizes, int n_in,
                              void* d_out, int out_size)
{
    const float* x   = (const float*)d_in[0];
    const float* h   = (const float*)d_in[1];
    const int*   src = (const int*)  d_in[2];
    const int*   dst = (const int*)  d_in[3];
    const float* Wg  = (const float*)d_in[4];
    const float* bg  = (const float*)d_in[5];
    const float* Wc  = (const float*)d_in[6];
    const float* bc  = (const float*)d_in[7];
    float* out = (float*)d_out;

    int n = in_sizes[0] / 64;
    int E = in_sizes[2];

    cudaFuncSetAttribute(k_gemm1,      cudaFuncAttributeMaxDynamicSharedMemorySize, G1_SMEM * 4);
    cudaFuncSetAttribute(k_gate_gemm2, cudaFuncAttributeMaxDynamicSharedMemorySize, G2_SMEM * 4);

    int nb;
    nb = (n * 48 + 255) / 256;         k_zero   <<<nb, 256>>>(n);
    nb = (E + 255) / 256;              k_degree <<<nb, 256>>>(src, dst, E);
    nb = (n + 255) / 256;              k_rsqrt  <<<nb, 256>>>(n);

    int tiles = (n + 63) / 64;
    k_gemm1<<<tiles, 256, G1_SMEM * 4>>>(x, h, Wg, n);

    nb = (int)(((long long)E * 32 + 255) / 256);
    k_scatter1<<<nb, 256>>>(src, dst, E);

    k_gate_gemm2<<<tiles, 256, G2_SMEM * 4>>>(x, h, Wc, bg, n);

    nb = (int)(((long long)E * 16 + 255) / 256);
    k_scatter2<<<nb, 256>>>(src, dst, E);

    nb = (n * 64 + 255) / 256;
    k_final<<<nb, 256>>>(h, bc, out, n);
}

// round 2
// speedup vs baseline: 1.2789x; 1.2789x over previous
#include <cuda_runtime.h>
#include <math.h>
#include <stdint.h>

#define NMAX 100000

// Scratch (allocation-free rule: __device__ globals)
__device__ float g_s_out[NMAX];
__device__ float g_s_in [NMAX];
__device__ float g_xw1 [(size_t)NMAX * 128];
__device__ float g_agg1[(size_t)NMAX * 128];
__device__ float g_xw2 [(size_t)NMAX * 64];
__device__ float g_agg2[(size_t)NMAX * 64];
__device__ float g_z   [(size_t)NMAX * 64];
__device__ float g_rh  [(size_t)NMAX * 64];

// ---------------------------------------------------------------------------
__global__ void k_zero(int n) {
    int i = blockIdx.x * blockDim.x + threadIdx.x;
    int n32 = n * 32;
    int n48 = n * 48;
    float4 z4 = make_float4(0.f, 0.f, 0.f, 0.f);
    if (i < n32)       ((float4*)g_agg1)[i] = z4;
    else if (i < n48)  ((float4*)g_agg2)[i - n32] = z4;
    if (i < n) { g_s_out[i] = 0.f; g_s_in[i] = 0.f; }
}

__global__ void k_degree(const int* __restrict__ src, const int* __restrict__ dst, int E) {
    int e = blockIdx.x * blockDim.x + threadIdx.x;
    if (e < E) {
        atomicAdd(&g_s_out[src[e]], 1.f);
        atomicAdd(&g_s_in [dst[e]], 1.f);
    }
}

__global__ void k_rsqrt(int n) {
    int i = blockIdx.x * blockDim.x + threadIdx.x;
    if (i < n) {
        g_s_out[i] = rsqrtf(fmaxf(g_s_out[i], 1.f));
        g_s_in [i] = rsqrtf(fmaxf(g_s_in [i], 1.f));
    }
}

// ---------------------------------------------------------------------------
// GEMM1: xw1[N,128] = diag(s_out)*[x|h] @ Wg[128,128]
// BM=128, BN=128, BK=16; 256 thr; 8x8 micro-tile (cols tc*4 and 64+tc*4)
// ---------------------------------------------------------------------------
__global__ __launch_bounds__(256, 2) void k_gemm1(
    const float* __restrict__ x, const float* __restrict__ h,
    const float* __restrict__ Wg, int n)
{
    __shared__ float Asm[16][132];
    __shared__ float Wsm[16][128];
    int t = threadIdx.x;
    int row0 = blockIdx.x * 128;
    int tr = t >> 4, tc = t & 15;

    float acc0[8][4], acc1[8][4];
#pragma unroll
    for (int i = 0; i < 8; i++)
#pragma unroll
        for (int j = 0; j < 4; j++) { acc0[i][j] = 0.f; acc1[i][j] = 0.f; }

    for (int k0 = 0; k0 < 128; k0 += 16) {
        // stage A (scaled) transposed into Asm[k][m]
#pragma unroll
        for (int half = 0; half < 2; half++) {
            int q = t + half * 256;
            int m = q >> 2, kq = q & 3;
            int gr = row0 + m;
            float4 v = make_float4(0.f, 0.f, 0.f, 0.f);
            if (gr < n) {
                int kk = k0 + kq * 4;
                const float* src = (kk < 64) ? (x + (size_t)gr * 64 + kk)
                                             : (h + (size_t)gr * 64 + kk - 64);
                v = *(const float4*)src;
                float s = g_s_out[gr];
                v.x *= s; v.y *= s; v.z *= s; v.w *= s;
            }
            Asm[kq * 4 + 0][m] = v.x;
            Asm[kq * 4 + 1][m] = v.y;
            Asm[kq * 4 + 2][m] = v.z;
            Asm[kq * 4 + 3][m] = v.w;
        }
        // stage W
#pragma unroll
        for (int half = 0; half < 2; half++) {
            int q = t + half * 256;
            int k = q >> 5, c4 = q & 31;
            *(float4*)(&Wsm[k][c4 * 4]) =
                *(const float4*)(Wg + (size_t)(k0 + k) * 128 + c4 * 4);
        }
        __syncthreads();

#pragma unroll
        for (int kk = 0; kk < 16; kk++) {
            float4 a0 = *(const float4*)(&Asm[kk][tr * 8]);
            float4 a1 = *(const float4*)(&Asm[kk][tr * 8 + 4]);
            float4 w0 = *(const float4*)(&Wsm[kk][tc * 4]);
            float4 w1 = *(const float4*)(&Wsm[kk][64 + tc * 4]);
            float a[8] = {a0.x, a0.y, a0.z, a0.w, a1.x, a1.y, a1.z, a1.w};
            float wa[4] = {w0.x, w0.y, w0.z, w0.w};
            float wb[4] = {w1.x, w1.y, w1.z, w1.w};
#pragma unroll
            for (int i = 0; i < 8; i++)
#pragma unroll
                for (int j = 0; j < 4; j++) {
                    acc0[i][j] += a[i] * wa[j];
                    acc1[i][j] += a[i] * wb[j];
                }
        }
        __syncthreads();
    }

#pragma unroll
    for (int i = 0; i < 8; i++) {
        int gr = row0 + tr * 8 + i;
        if (gr < n) {
            *(float4*)(g_xw1 + (size_t)gr * 128 + tc * 4) =
                make_float4(acc0[i][0], acc0[i][1], acc0[i][2], acc0[i][3]);
            *(float4*)(g_xw1 + (size_t)gr * 128 + 64 + tc * 4) =
                make_float4(acc1[i][0], acc1[i][1], acc1[i][2], acc1[i][3]);
        }
    }
}

// ---------------------------------------------------------------------------
// Scatter1: agg1[dst] += xw1[src]
// ---------------------------------------------------------------------------
__global__ __launch_bounds__(256) void k_scatter1(
    const int* __restrict__ src, const int* __restrict__ dst, int E)
{
    int gt = blockIdx.x * blockDim.x + threadIdx.x;
    int e = gt >> 5;
    if (e >= E) return;
    int lane = gt & 31;
    int s = __ldg(src + e);
    int d = __ldg(dst + e);
    float4 v = __ldg((const float4*)(g_xw1 + (size_t)s * 128) + lane);
    float* p = g_agg1 + (size_t)d * 128 + lane * 4;
    asm volatile("red.global.add.v4.f32 [%0], {%1,%2,%3,%4};"
                 :: "l"(p), "f"(v.x), "f"(v.y), "f"(v.z), "f"(v.w) : "memory");
}

// ---------------------------------------------------------------------------
// Gates: r,z = sigmoid(agg1 * s_in + b); store z and rh = r*h
// ---------------------------------------------------------------------------
__global__ void k_gates(const float* __restrict__ h, const float* __restrict__ bg, int n) {
    int t = blockIdx.x * blockDim.x + threadIdx.x;   // over n*16 quads
    if (t >= n * 16) return;
    int i = t >> 4, q = t & 15;
    int j = q * 4;
    float si = g_s_in[i];
    float4 ar = *(const float4*)(g_agg1 + (size_t)i * 128 + j);
    float4 az = *(const float4*)(g_agg1 + (size_t)i * 128 + 64 + j);
    float4 br = *(const float4*)(bg + j);
    float4 bz = *(const float4*)(bg + 64 + j);
    float4 h4 = *(const float4*)(h + (size_t)i * 64 + j);
    float4 rg, zg;
    rg.x = 1.f / (1.f + expf(-(ar.x * si + br.x)));
    rg.y = 1.f / (1.f + expf(-(ar.y * si + br.y)));
    rg.z = 1.f / (1.f + expf(-(ar.z * si + br.z)));
    rg.w = 1.f / (1.f + expf(-(ar.w * si + br.w)));
    zg.x = 1.f / (1.f + expf(-(az.x * si + bz.x)));
    zg.y = 1.f / (1.f + expf(-(az.y * si + bz.y)));
    zg.z = 1.f / (1.f + expf(-(az.z * si + bz.z)));
    zg.w = 1.f / (1.f + expf(-(az.w * si + bz.w)));
    *(float4*)(g_z  + (size_t)i * 64 + j) = zg;
    *(float4*)(g_rh + (size_t)i * 64 + j) =
        make_float4(rg.x * h4.x, rg.y * h4.y, rg.z * h4.z, rg.w * h4.w);
}

// ---------------------------------------------------------------------------
// GEMM2: xw2[N,64] = diag(s_out)*[x|rh] @ Wc[128,64]
// BM=128, BN=64, BK=16; 256 thr; 4x8 micro-tile (cols tc*4 and 32+tc*4)
// ---------------------------------------------------------------------------
__global__ __launch_bounds__(256, 2) void k_gemm2(
    const float* __restrict__ x, const float* __restrict__ Wc, int n)
{
    __shared__ float Asm[16][132];
    __shared__ float Wsm[16][64];
    int t = threadIdx.x;
    int row0 = blockIdx.x * 128;
    int tr = t >> 3, tc = t & 7;

    float acc0[4][4], acc1[4][4];
#pragma unroll
    for (int i = 0; i < 4; i++)
#pragma unroll
        for (int j = 0; j < 4; j++) { acc0[i][j] = 0.f; acc1[i][j] = 0.f; }

    for (int k0 = 0; k0 < 128; k0 += 16) {
#pragma unroll
        for (int half = 0; half < 2; half++) {
            int q = t + half * 256;
            int m = q >> 2, kq = q & 3;
            int gr = row0 + m;
            float4 v = make_float4(0.f, 0.f, 0.f, 0.f);
            if (gr < n) {
                int kk = k0 + kq * 4;
                const float* src = (kk < 64) ? (x + (size_t)gr * 64 + kk)
                                             : (g_rh + (size_t)gr * 64 + kk - 64);
                v = *(const float4*)src;
                float s = g_s_out[gr];
                v.x *= s; v.y *= s; v.z *= s; v.w *= s;
            }
            Asm[kq * 4 + 0][m] = v.x;
            Asm[kq * 4 + 1][m] = v.y;
            Asm[kq * 4 + 2][m] = v.z;
            Asm[kq * 4 + 3][m] = v.w;
        }
        {
            int k = t >> 4, c4 = t & 15;
            *(float4*)(&Wsm[k][c4 * 4]) =
                *(const float4*)(Wc + (size_t)(k0 + k) * 64 + c4 * 4);
        }
        __syncthreads();

#pragma unroll
        for (int kk = 0; kk < 16; kk++) {
            float4 av = *(const float4*)(&Asm[kk][tr * 4]);
            float4 w0 = *(const float4*)(&Wsm[kk][tc * 4]);
            float4 w1 = *(const float4*)(&Wsm[kk][32 + tc * 4]);
            float a[4] = {av.x, av.y, av.z, av.w};
            float wa[4] = {w0.x, w0.y, w0.z, w0.w};
            float wb[4] = {w1.x, w1.y, w1.z, w1.w};
#pragma unroll
            for (int i = 0; i < 4; i++)
#pragma unroll
                for (int j = 0; j < 4; j++) {
                    acc0[i][j] += a[i] * wa[j];
                    acc1[i][j] += a[i] * wb[j];
                }
        }
        __syncthreads();
    }

#pragma unroll
    for (int i = 0; i < 4; i++) {
        int gr = row0 + tr * 4 + i;
        if (gr < n) {
            *(float4*)(g_xw2 + (size_t)gr * 64 + tc * 4) =
                make_float4(acc0[i][0], acc0[i][1], acc0[i][2], acc0[i][3]);
            *(float4*)(g_xw2 + (size_t)gr * 64 + 32 + tc * 4) =
                make_float4(acc1[i][0], acc1[i][1], acc1[i][2], acc1[i][3]);
        }
    }
}

// ---------------------------------------------------------------------------
// Scatter2: agg2[dst] += xw2[src]
// ---------------------------------------------------------------------------
__global__ __launch_bounds__(256) void k_scatter2(
    const int* __restrict__ src, const int* __restrict__ dst, int E)
{
    int gt = blockIdx.x * blockDim.x + threadIdx.x;
    int e = gt >> 4;
    if (e >= E) return;
    int q = gt & 15;
    int s = __ldg(src + e);
    int d = __ldg(dst + e);
    float4 v = __ldg((const float4*)(g_xw2 + (size_t)s * 64) + q);
    float* p = g_agg2 + (size_t)d * 64 + q * 4;
    asm volatile("red.global.add.v4.f32 [%0], {%1,%2,%3,%4};"
                 :: "l"(p), "f"(v.x), "f"(v.y), "f"(v.z), "f"(v.w) : "memory");
}

// ---------------------------------------------------------------------------
__global__ void k_final(const float* __restrict__ h, const float* __restrict__ bc,
                        float* __restrict__ out, int n)
{
    int t = blockIdx.x * blockDim.x + threadIdx.x;
    if (t < n * 64) {
        int i = t >> 6, j = t & 63;
        float c = g_agg2[t] * g_s_in[i] + __ldg(bc + j);
        float z = g_z[t];
        out[t] = z * h[t] + (1.f - z) * tanhf(c);
    }
}

// ---------------------------------------------------------------------------
extern "C" void kernel_launch(void* const* d_in, const int* in_sizes, int n_in,
                              void* d_out, int out_size)
{
    const float* x   = (const float*)d_in[0];
    const float* h   = (const float*)d_in[1];
    const int*   src = (const int*)  d_in[2];
    const int*   dst = (const int*)  d_in[3];
    const float* Wg  = (const float*)d_in[4];
    const float* bg  = (const float*)d_in[5];
    const float* Wc  = (const float*)d_in[6];
    const float* bc  = (const float*)d_in[7];
    float* out = (float*)d_out;

    int n = in_sizes[0] / 64;
    int E = in_sizes[2];

    int nb;
    nb = (n * 48 + 255) / 256;         k_zero   <<<nb, 256>>>(n);
    nb = (E + 255) / 256;              k_degree <<<nb, 256>>>(src, dst, E);
    nb = (n + 255) / 256;              k_rsqrt  <<<nb, 256>>>(n);

    int tiles = (n + 127) / 128;
    k_gemm1<<<tiles, 256>>>(x, h, Wg, n);

    nb = (int)(((long long)E * 32 + 255) / 256);
    k_scatter1<<<nb, 256>>>(src, dst, E);

    nb = (n * 16 + 255) / 256;
    k_gates<<<nb, 256>>>(h, bg, n);

    k_gemm2<<<tiles, 256>>>(x, Wc, n);

    nb = (int)(((long long)E * 16 + 255) / 256);
    k_scatter2<<<nb, 256>>>(src, dst, E);

    nb = (n * 64 + 255) / 256;
    k_final<<<nb, 256>>>(h, bc, out, n);
}

// round 3
// speedup vs baseline: 2.2581x; 1.7657x over previous
#include <cuda_runtime.h>
#include <math.h>
#include <stdint.h>

#define NMAX 100000
#define EMAX 2000000

// Scratch (allocation-free rule: __device__ globals)
__device__ int   g_deg_in [NMAX];
__device__ int   g_deg_out[NMAX];
__device__ float g_s_out[NMAX];
__device__ float g_s_in [NMAX];
__device__ int   g_row   [NMAX + 1];
__device__ int   g_cursor[NMAX];
__device__ int   g_bsum  [128];
__device__ int   g_esrc  [EMAX];
__device__ float g_xw1 [(size_t)NMAX * 128];
__device__ float g_xw2 [(size_t)NMAX * 64];
__device__ float g_z   [(size_t)NMAX * 64];
__device__ float g_rh  [(size_t)NMAX * 64];

// ---------------------------------------------------------------------------
__global__ void k_zero(int n) {
    int i = blockIdx.x * blockDim.x + threadIdx.x;
    if (i < n) { g_deg_in[i] = 0; g_deg_out[i] = 0; }
}

__global__ void k_degree(const int* __restrict__ src, const int* __restrict__ dst, int E) {
    int e = blockIdx.x * blockDim.x + threadIdx.x;
    if (e < E) {
        atomicAdd(&g_deg_out[src[e]], 1);
        atomicAdd(&g_deg_in [dst[e]], 1);
    }
}

__global__ void k_rsqrt(int n) {
    int i = blockIdx.x * blockDim.x + threadIdx.x;
    if (i < n) {
        g_s_out[i] = rsqrtf(fmaxf((float)g_deg_out[i], 1.f));
        g_s_in [i] = rsqrtf(fmaxf((float)g_deg_in [i], 1.f));
    }
}

// ---------------------------------------------------------------------------
// Prefix scan of deg_in -> g_row (exclusive), g_cursor = g_row
// ---------------------------------------------------------------------------
__global__ __launch_bounds__(1024) void k_scan1(int n) {
    int t = threadIdx.x;
    int i = blockIdx.x * 1024 + t;
    int v = (i < n) ? g_deg_in[i] : 0;
    // warp reduce
    for (int o = 16; o > 0; o >>= 1) v += __shfl_down_sync(~0u, v, o);
    __shared__ int ws[32];
    if ((t & 31) == 0) ws[t >> 5] = v;
    __syncthreads();
    if (t < 32) {
        int u = ws[t];
        for (int o = 16; o > 0; o >>= 1) u += __shfl_down_sync(~0u, u, o);
        if (t == 0) g_bsum[blockIdx.x] = u;
    }
}

__global__ void k_scan2(int nb, int n) {
    int t = threadIdx.x;   // 128 threads
    __shared__ int s[128];
    int v = (t < nb) ? g_bsum[t] : 0;
    s[t] = v;
    __syncthreads();
    for (int o = 1; o < 128; o <<= 1) {
        int u = (t >= o) ? s[t - o] : 0;
        __syncthreads();
        s[t] += u;
        __syncthreads();
    }
    if (t < nb) g_bsum[t] = s[t] - v;           // exclusive
    if (t == nb - 1) g_row[n] = s[t];           // total = E
}

__global__ __launch_bounds__(1024) void k_scan3(int n) {
    int t = threadIdx.x;
    int i = blockIdx.x * 1024 + t;
    int v = (i < n) ? g_deg_in[i] : 0;
    int lane = t & 31, wid = t >> 5;
    int inc = v;
    for (int o = 1; o < 32; o <<= 1) {
        int u = __shfl_up_sync(~0u, inc, o);
        if (lane >= o) inc += u;
    }
    __shared__ int ws[32];
    if (lane == 31) ws[wid] = inc;
    __syncthreads();
    if (t < 32) {
        int u = ws[t];
        for (int o = 1; o < 32; o <<= 1) {
            int w = __shfl_up_sync(~0u, u, o);
            if (t >= o) u += w;
        }
        ws[t] = u;
    }
    __syncthreads();
    int excl = inc - v + (wid > 0 ? ws[wid - 1] : 0) + g_bsum[blockIdx.x];
    if (i < n) { g_row[i] = excl; g_cursor[i] = excl; }
}

__global__ void k_bucket(const int* __restrict__ src, const int* __restrict__ dst, int E) {
    int e = blockIdx.x * blockDim.x + threadIdx.x;
    if (e < E) {
        int p = atomicAdd(&g_cursor[dst[e]], 1);
        g_esrc[p] = src[e];
    }
}

// ---------------------------------------------------------------------------
// GEMM1: xw1[N,128] = diag(s_out)*[x|h] @ Wg[128,128]
// ---------------------------------------------------------------------------
__global__ __launch_bounds__(256, 2) void k_gemm1(
    const float* __restrict__ x, const float* __restrict__ h,
    const float* __restrict__ Wg, int n)
{
    __shared__ float Asm[16][132];
    __shared__ float Wsm[16][128];
    int t = threadIdx.x;
    int row0 = blockIdx.x * 128;
    int tr = t >> 4, tc = t & 15;

    float acc0[8][4], acc1[8][4];
#pragma unroll
    for (int i = 0; i < 8; i++)
#pragma unroll
        for (int j = 0; j < 4; j++) { acc0[i][j] = 0.f; acc1[i][j] = 0.f; }

    for (int k0 = 0; k0 < 128; k0 += 16) {
#pragma unroll
        for (int half = 0; half < 2; half++) {
            int q = t + half * 256;
            int m = q >> 2, kq = q & 3;
            int gr = row0 + m;
            float4 v = make_float4(0.f, 0.f, 0.f, 0.f);
            if (gr < n) {
                int kk = k0 + kq * 4;
                const float* src = (kk < 64) ? (x + (size_t)gr * 64 + kk)
                                             : (h + (size_t)gr * 64 + kk - 64);
                v = *(const float4*)src;
                float s = g_s_out[gr];
                v.x *= s; v.y *= s; v.z *= s; v.w *= s;
            }
            Asm[kq * 4 + 0][m] = v.x;
            Asm[kq * 4 + 1][m] = v.y;
            Asm[kq * 4 + 2][m] = v.z;
            Asm[kq * 4 + 3][m] = v.w;
        }
#pragma unroll
        for (int half = 0; half < 2; half++) {
            int q = t + half * 256;
            int k = q >> 5, c4 = q & 31;
            *(float4*)(&Wsm[k][c4 * 4]) =
                *(const float4*)(Wg + (size_t)(k0 + k) * 128 + c4 * 4);
        }
        __syncthreads();

#pragma unroll
        for (int kk = 0; kk < 16; kk++) {
            float4 a0 = *(const float4*)(&Asm[kk][tr * 8]);
            float4 a1 = *(const float4*)(&Asm[kk][tr * 8 + 4]);
            float4 w0 = *(const float4*)(&Wsm[kk][tc * 4]);
            float4 w1 = *(const float4*)(&Wsm[kk][64 + tc * 4]);
            float a[8] = {a0.x, a0.y, a0.z, a0.w, a1.x, a1.y, a1.z, a1.w};
            float wa[4] = {w0.x, w0.y, w0.z, w0.w};
            float wb[4] = {w1.x, w1.y, w1.z, w1.w};
#pragma unroll
            for (int i = 0; i < 8; i++)
#pragma unroll
                for (int j = 0; j < 4; j++) {
                    acc0[i][j] += a[i] * wa[j];
                    acc1[i][j] += a[i] * wb[j];
                }
        }
        __syncthreads();
    }

#pragma unroll
    for (int i = 0; i < 8; i++) {
        int gr = row0 + tr * 8 + i;
        if (gr < n) {
            *(float4*)(g_xw1 + (size_t)gr * 128 + tc * 4) =
                make_float4(acc0[i][0], acc0[i][1], acc0[i][2], acc0[i][3]);
            *(float4*)(g_xw1 + (size_t)gr * 128 + 64 + tc * 4) =
                make_float4(acc1[i][0], acc1[i][1], acc1[i][2], acc1[i][3]);
        }
    }
}

// ---------------------------------------------------------------------------
// Agg1 + gates fused: warp per node.
// acc[128] = sum_{e in-edges} xw1[src[e]]; g = sigmoid(acc*s_in + bg);
// lanes 0-15: rh = r * h ; lanes 16-31: store z.
// ---------------------------------------------------------------------------
__global__ __launch_bounds__(256) void k_agg1_gates(
    const float* __restrict__ h, const float* __restrict__ bg, int n)
{
    int gt = blockIdx.x * blockDim.x + threadIdx.x;
    int i = gt >> 5;
    if (i >= n) return;
    int lane = gt & 31;

    int p   = g_row[i];
    int end = g_row[i + 1];
    float4 acc = make_float4(0.f, 0.f, 0.f, 0.f);
    for (; p + 4 <= end; p += 4) {
        int s0 = __ldg(g_esrc + p);
        int s1 = __ldg(g_esrc + p + 1);
        int s2 = __ldg(g_esrc + p + 2);
        int s3 = __ldg(g_esrc + p + 3);
        float4 v0 = __ldg((const float4*)(g_xw1 + (size_t)s0 * 128) + lane);
        float4 v1 = __ldg((const float4*)(g_xw1 + (size_t)s1 * 128) + lane);
        float4 v2 = __ldg((const float4*)(g_xw1 + (size_t)s2 * 128) + lane);
        float4 v3 = __ldg((const float4*)(g_xw1 + (size_t)s3 * 128) + lane);
        acc.x += (v0.x + v1.x) + (v2.x + v3.x);
        acc.y += (v0.y + v1.y) + (v2.y + v3.y);
        acc.z += (v0.z + v1.z) + (v2.z + v3.z);
        acc.w += (v0.w + v1.w) + (v2.w + v3.w);
    }
    for (; p < end; p++) {
        int s0 = __ldg(g_esrc + p);
        float4 v0 = __ldg((const float4*)(g_xw1 + (size_t)s0 * 128) + lane);
        acc.x += v0.x; acc.y += v0.y; acc.z += v0.z; acc.w += v0.w;
    }

    float si = g_s_in[i];
    float4 b4 = __ldg((const float4*)bg + lane);
    float4 g;
    g.x = 1.f / (1.f + expf(-(acc.x * si + b4.x)));
    g.y = 1.f / (1.f + expf(-(acc.y * si + b4.y)));
    g.z = 1.f / (1.f + expf(-(acc.z * si + b4.z)));
    g.w = 1.f / (1.f + expf(-(acc.w * si + b4.w)));

    if (lane < 16) {
        float4 h4 = __ldg((const float4*)(h + (size_t)i * 64) + lane);
        *((float4*)(g_rh + (size_t)i * 64) + lane) =
            make_float4(g.x * h4.x, g.y * h4.y, g.z * h4.z, g.w * h4.w);
    } else {
        *((float4*)(g_z + (size_t)i * 64) + (lane - 16)) = g;
    }
}

// ---------------------------------------------------------------------------
// GEMM2: xw2[N,64] = diag(s_out)*[x|rh] @ Wc[128,64]
// ---------------------------------------------------------------------------
__global__ __launch_bounds__(256, 2) void k_gemm2(
    const float* __restrict__ x, const float* __restrict__ Wc, int n)
{
    __shared__ float Asm[16][132];
    __shared__ float Wsm[16][64];
    int t = threadIdx.x;
    int row0 = blockIdx.x * 128;
    int tr = t >> 3, tc = t & 7;

    float acc0[4][4], acc1[4][4];
#pragma unroll
    for (int i = 0; i < 4; i++)
#pragma unroll
        for (int j = 0; j < 4; j++) { acc0[i][j] = 0.f; acc1[i][j] = 0.f; }

    for (int k0 = 0; k0 < 128; k0 += 16) {
#pragma unroll
        for (int half = 0; half < 2; half++) {
            int q = t + half * 256;
            int m = q >> 2, kq = q & 3;
            int gr = row0 + m;
            float4 v = make_float4(0.f, 0.f, 0.f, 0.f);
            if (gr < n) {
                int kk = k0 + kq * 4;
                const float* src = (kk < 64) ? (x + (size_t)gr * 64 + kk)
                                             : (g_rh + (size_t)gr * 64 + kk - 64);
                v = *(const float4*)src;
                float s = g_s_out[gr];
                v.x *= s; v.y *= s; v.z *= s; v.w *= s;
            }
            Asm[kq * 4 + 0][m] = v.x;
            Asm[kq * 4 + 1][m] = v.y;
            Asm[kq * 4 + 2][m] = v.z;
            Asm[kq * 4 + 3][m] = v.w;
        }
        {
            int k = t >> 4, c4 = t & 15;
            *(float4*)(&Wsm[k][c4 * 4]) =
                *(const float4*)(Wc + (size_t)(k0 + k) * 64 + c4 * 4);
        }
        __syncthreads();

#pragma unroll
        for (int kk = 0; kk < 16; kk++) {
            float4 av = *(const float4*)(&Asm[kk][tr * 4]);
            float4 w0 = *(const float4*)(&Wsm[kk][tc * 4]);
            float4 w1 = *(const float4*)(&Wsm[kk][32 + tc * 4]);
            float a[4] = {av.x, av.y, av.z, av.w};
            float wa[4] = {w0.x, w0.y, w0.z, w0.w};
            float wb[4] = {w1.x, w1.y, w1.z, w1.w};
#pragma unroll
            for (int i = 0; i < 4; i++)
#pragma unroll
                for (int j = 0; j < 4; j++) {
                    acc0[i][j] += a[i] * wa[j];
                    acc1[i][j] += a[i] * wb[j];
                }
        }
        __syncthreads();
    }

#pragma unroll
    for (int i = 0; i < 4; i++) {
        int gr = row0 + tr * 4 + i;
        if (gr < n) {
            *(float4*)(g_xw2 + (size_t)gr * 64 + tc * 4) =
                make_float4(acc0[i][0], acc0[i][1], acc0[i][2], acc0[i][3]);
            *(float4*)(g_xw2 + (size_t)gr * 64 + 32 + tc * 4) =
                make_float4(acc1[i][0], acc1[i][1], acc1[i][2], acc1[i][3]);
        }
    }
}

// ---------------------------------------------------------------------------
// Agg2 + GRU epilogue fused: 16 lanes per node.
// c = sum xw2[src] * s_in + bc ; out = z*h + (1-z)*tanh(c)
// ---------------------------------------------------------------------------
__global__ __launch_bounds__(256) void k_agg2_final(
    const float* __restrict__ h, const float* __restrict__ bc,
    float* __restrict__ out, int n)
{
    int gt = blockIdx.x * blockDim.x + threadIdx.x;
    int i = gt >> 4;
    if (i >= n) return;
    int q = gt & 15;

    int p   = g_row[i];
    int end = g_row[i + 1];
    float4 acc = make_float4(0.f, 0.f, 0.f, 0.f);
    for (; p + 4 <= end; p += 4) {
        int s0 = __ldg(g_esrc + p);
        int s1 = __ldg(g_esrc + p + 1);
        int s2 = __ldg(g_esrc + p + 2);
        int s3 = __ldg(g_esrc + p + 3);
        float4 v0 = __ldg((const float4*)(g_xw2 + (size_t)s0 * 64) + q);
        float4 v1 = __ldg((const float4*)(g_xw2 + (size_t)s1 * 64) + q);
        float4 v2 = __ldg((const float4*)(g_xw2 + (size_t)s2 * 64) + q);
        float4 v3 = __ldg((const float4*)(g_xw2 + (size_t)s3 * 64) + q);
        acc.x += (v0.x + v1.x) + (v2.x + v3.x);
        acc.y += (v0.y + v1.y) + (v2.y + v3.y);
        acc.z += (v0.z + v1.z) + (v2.z + v3.z);
        acc.w += (v0.w + v1.w) + (v2.w + v3.w);
    }
    for (; p < end; p++) {
        int s0 = __ldg(g_esrc + p);
        float4 v0 = __ldg((const float4*)(g_xw2 + (size_t)s0 * 64) + q);
        acc.x += v0.x; acc.y += v0.y; acc.z += v0.z; acc.w += v0.w;
    }

    float si = g_s_in[i];
    float4 b4 = __ldg((const float4*)bc + q);
    float4 z4 = *((const float4*)(g_z + (size_t)i * 64) + q);
    float4 h4 = __ldg((const float4*)(h + (size_t)i * 64) + q);
    float4 o;
    o.x = z4.x * h4.x + (1.f - z4.x) * tanhf(acc.x * si + b4.x);
    o.y = z4.y * h4.y + (1.f - z4.y) * tanhf(acc.y * si + b4.y);
    o.z = z4.z * h4.z + (1.f - z4.z) * tanhf(acc.z * si + b4.z);
    o.w = z4.w * h4.w + (1.f - z4.w) * tanhf(acc.w * si + b4.w);
    *((float4*)(out + (size_t)i * 64) + q) = o;
}

// ---------------------------------------------------------------------------
extern "C" void kernel_launch(void* const* d_in, const int* in_sizes, int n_in,
                              void* d_out, int out_size)
{
    const float* x   = (const float*)d_in[0];
    const float* h   = (const float*)d_in[1];
    const int*   src = (const int*)  d_in[2];
    const int*   dst = (const int*)  d_in[3];
    const float* Wg  = (const float*)d_in[4];
    const float* bg  = (const float*)d_in[5];
    const float* Wc  = (const float*)d_in[6];
    const float* bc  = (const float*)d_in[7];
    float* out = (float*)d_out;

    int n = in_sizes[0] / 64;
    int E = in_sizes[2];
    int NB = (n + 1023) / 1024;

    int nb;
    nb = (n + 255) / 256;              k_zero   <<<nb, 256>>>(n);
    nb = (E + 255) / 256;              k_degree <<<nb, 256>>>(src, dst, E);
    nb = (n + 255) / 256;              k_rsqrt  <<<nb, 256>>>(n);

    k_scan1<<<NB, 1024>>>(n);
    k_scan2<<<1, 128>>>(NB, n);
    k_scan3<<<NB, 1024>>>(n);
    nb = (E + 255) / 256;              k_bucket <<<nb, 256>>>(src, dst, E);

    int tiles = (n + 127) / 128;
    k_gemm1<<<tiles, 256>>>(x, h, Wg, n);

    nb = (int)(((long long)n * 32 + 255) / 256);
    k_agg1_gates<<<nb, 256>>>(h, bg, n);

    k_gemm2<<<tiles, 256>>>(x, Wc, n);

    nb = (int)(((long long)n * 16 + 255) / 256);
    k_agg2_final<<<nb, 256>>>(h, bc, out, n);
}

// round 4
// speedup vs baseline: 2.4190x; 1.0712x over previous
#include <cuda_runtime.h>
#include <cuda_fp16.h>
#include <math.h>
#include <stdint.h>

#define NMAX 100000
#define EMAX 2000000

// Scratch (allocation-free rule: __device__ globals)
__device__ int    g_deg_in [NMAX];
__device__ int    g_deg_out[NMAX];
__device__ float  g_s_out[NMAX];
__device__ float  g_s_in [NMAX];
__device__ int    g_row   [NMAX + 1];
__device__ int    g_cursor[NMAX];
__device__ int    g_bsum  [128];
__device__ int    g_esrc  [EMAX];
__device__ __half g_xw1h[(size_t)NMAX * 128];
__device__ __half g_xw2h[(size_t)NMAX * 64];
__device__ float  g_z   [(size_t)NMAX * 64];
__device__ float  g_rh  [(size_t)NMAX * 64];

// ---------------------------------------------------------------------------
__global__ void k_zero(int n) {
    int i = blockIdx.x * blockDim.x + threadIdx.x;
    if (i < n) { g_deg_in[i] = 0; g_deg_out[i] = 0; }
}

__global__ void k_degree(const int* __restrict__ src, const int* __restrict__ dst, int E) {
    int e = blockIdx.x * blockDim.x + threadIdx.x;
    if (e < E) {
        atomicAdd(&g_deg_out[src[e]], 1);
        atomicAdd(&g_deg_in [dst[e]], 1);
    }
}

// ---------------------------------------------------------------------------
// Prefix scan of deg_in -> g_row (exclusive), g_cursor = g_row; also rsqrt
// ---------------------------------------------------------------------------
__global__ __launch_bounds__(1024) void k_scan1(int n) {
    int t = threadIdx.x;
    int i = blockIdx.x * 1024 + t;
    int v = (i < n) ? g_deg_in[i] : 0;
    for (int o = 16; o > 0; o >>= 1) v += __shfl_down_sync(~0u, v, o);
    __shared__ int ws[32];
    if ((t & 31) == 0) ws[t >> 5] = v;
    __syncthreads();
    if (t < 32) {
        int u = ws[t];
        for (int o = 16; o > 0; o >>= 1) u += __shfl_down_sync(~0u, u, o);
        if (t == 0) g_bsum[blockIdx.x] = u;
    }
}

__global__ void k_scan2(int nb, int n) {
    int t = threadIdx.x;   // 128 threads
    __shared__ int s[128];
    int v = (t < nb) ? g_bsum[t] : 0;
    s[t] = v;
    __syncthreads();
    for (int o = 1; o < 128; o <<= 1) {
        int u = (t >= o) ? s[t - o] : 0;
        __syncthreads();
        s[t] += u;
        __syncthreads();
    }
    if (t < nb) g_bsum[t] = s[t] - v;           // exclusive
    if (t == nb - 1) g_row[n] = s[t];
}

__global__ __launch_bounds__(1024) void k_scan3(int n) {
    int t = threadIdx.x;
    int i = blockIdx.x * 1024 + t;
    int v = (i < n) ? g_deg_in[i] : 0;
    int lane = t & 31, wid = t >> 5;
    int inc = v;
    for (int o = 1; o < 32; o <<= 1) {
        int u = __shfl_up_sync(~0u, inc, o);
        if (lane >= o) inc += u;
    }
    __shared__ int ws[32];
    if (lane == 31) ws[wid] = inc;
    __syncthreads();
    if (t < 32) {
        int u = ws[t];
        for (int o = 1; o < 32; o <<= 1) {
            int w = __shfl_up_sync(~0u, u, o);
            if (t >= o) u += w;
        }
        ws[t] = u;
    }
    __syncthreads();
    int excl = inc - v + (wid > 0 ? ws[wid - 1] : 0) + g_bsum[blockIdx.x];
    if (i < n) {
        g_row[i] = excl;
        g_cursor[i] = excl;
        g_s_in [i] = rsqrtf(fmaxf((float)v, 1.f));
        g_s_out[i] = rsqrtf(fmaxf((float)g_deg_out[i], 1.f));
    }
}

__global__ void k_bucket(const int* __restrict__ src, const int* __restrict__ dst, int E) {
    int e = blockIdx.x * blockDim.x + threadIdx.x;
    if (e < E) {
        int p = atomicAdd(&g_cursor[dst[e]], 1);
        g_esrc[p] = src[e];
    }
}

// ---------------------------------------------------------------------------
// GEMM1: xw1[N,128] = diag(s_out)*[x|h] @ Wg[128,128]  (fp16 out)
// ---------------------------------------------------------------------------
__global__ __launch_bounds__(256, 2) void k_gemm1(
    const float* __restrict__ x, const float* __restrict__ h,
    const float* __restrict__ Wg, int n)
{
    __shared__ float Asm[16][132];
    __shared__ float Wsm[16][128];
    int t = threadIdx.x;
    int row0 = blockIdx.x * 128;
    int tr = t >> 4, tc = t & 15;

    float acc0[8][4], acc1[8][4];
#pragma unroll
    for (int i = 0; i < 8; i++)
#pragma unroll
        for (int j = 0; j < 4; j++) { acc0[i][j] = 0.f; acc1[i][j] = 0.f; }

    for (int k0 = 0; k0 < 128; k0 += 16) {
#pragma unroll
        for (int half = 0; half < 2; half++) {
            int q = t + half * 256;
            int m = q >> 2, kq = q & 3;
            int gr = row0 + m;
            float4 v = make_float4(0.f, 0.f, 0.f, 0.f);
            if (gr < n) {
                int kk = k0 + kq * 4;
                const float* src = (kk < 64) ? (x + (size_t)gr * 64 + kk)
                                             : (h + (size_t)gr * 64 + kk - 64);
                v = *(const float4*)src;
                float s = g_s_out[gr];
                v.x *= s; v.y *= s; v.z *= s; v.w *= s;
            }
            Asm[kq * 4 + 0][m] = v.x;
            Asm[kq * 4 + 1][m] = v.y;
            Asm[kq * 4 + 2][m] = v.z;
            Asm[kq * 4 + 3][m] = v.w;
        }
#pragma unroll
        for (int half = 0; half < 2; half++) {
            int q = t + half * 256;
            int k = q >> 5, c4 = q & 31;
            *(float4*)(&Wsm[k][c4 * 4]) =
                *(const float4*)(Wg + (size_t)(k0 + k) * 128 + c4 * 4);
        }
        __syncthreads();

#pragma unroll
        for (int kk = 0; kk < 16; kk++) {
            float4 a0 = *(const float4*)(&Asm[kk][tr * 8]);
            float4 a1 = *(const float4*)(&Asm[kk][tr * 8 + 4]);
            float4 w0 = *(const float4*)(&Wsm[kk][tc * 4]);
            float4 w1 = *(const float4*)(&Wsm[kk][64 + tc * 4]);
            float a[8] = {a0.x, a0.y, a0.z, a0.w, a1.x, a1.y, a1.z, a1.w};
            float wa[4] = {w0.x, w0.y, w0.z, w0.w};
            float wb[4] = {w1.x, w1.y, w1.z, w1.w};
#pragma unroll
            for (int i = 0; i < 8; i++)
#pragma unroll
                for (int j = 0; j < 4; j++) {
                    acc0[i][j] += a[i] * wa[j];
                    acc1[i][j] += a[i] * wb[j];
                }
        }
        __syncthreads();
    }

#pragma unroll
    for (int i = 0; i < 8; i++) {
        int gr = row0 + tr * 8 + i;
        if (gr < n) {
            __half2 p0 = __floats2half2_rn(acc0[i][0], acc0[i][1]);
            __half2 p1 = __floats2half2_rn(acc0[i][2], acc0[i][3]);
            __half2 p2 = __floats2half2_rn(acc1[i][0], acc1[i][1]);
            __half2 p3 = __floats2half2_rn(acc1[i][2], acc1[i][3]);
            uint2 u0 = make_uint2(*(unsigned*)&p0, *(unsigned*)&p1);
            uint2 u1 = make_uint2(*(unsigned*)&p2, *(unsigned*)&p3);
            *(uint2*)(g_xw1h + (size_t)gr * 128 + tc * 4)      = u0;
            *(uint2*)(g_xw1h + (size_t)gr * 128 + 64 + tc * 4) = u1;
        }
    }
}

// ---------------------------------------------------------------------------
// Agg1 + gates fused: warp per node (fp16 gathers, fp32 accum)
// ---------------------------------------------------------------------------
__global__ __launch_bounds__(256) void k_agg1_gates(
    const float* __restrict__ h, const float* __restrict__ bg, int n)
{
    int gt = blockIdx.x * blockDim.x + threadIdx.x;
    int i = gt >> 5;
    if (i >= n) return;
    int lane = gt & 31;

    int p   = g_row[i];
    int end = g_row[i + 1];
    float4 acc = make_float4(0.f, 0.f, 0.f, 0.f);
    for (; p + 4 <= end; p += 4) {
        int s0 = __ldg(g_esrc + p);
        int s1 = __ldg(g_esrc + p + 1);
        int s2 = __ldg(g_esrc + p + 2);
        int s3 = __ldg(g_esrc + p + 3);
        uint2 u0 = __ldg((const uint2*)(g_xw1h + (size_t)s0 * 128) + lane);
        uint2 u1 = __ldg((const uint2*)(g_xw1h + (size_t)s1 * 128) + lane);
        uint2 u2 = __ldg((const uint2*)(g_xw1h + (size_t)s2 * 128) + lane);
        uint2 u3 = __ldg((const uint2*)(g_xw1h + (size_t)s3 * 128) + lane);
        float2 a0 = __half22float2(*(__half2*)&u0.x), b0 = __half22float2(*(__half2*)&u0.y);
        float2 a1 = __half22float2(*(__half2*)&u1.x), b1 = __half22float2(*(__half2*)&u1.y);
        float2 a2 = __half22float2(*(__half2*)&u2.x), b2 = __half22float2(*(__half2*)&u2.y);
        float2 a3 = __half22float2(*(__half2*)&u3.x), b3 = __half22float2(*(__half2*)&u3.y);
        acc.x += (a0.x + a1.x) + (a2.x + a3.x);
        acc.y += (a0.y + a1.y) + (a2.y + a3.y);
        acc.z += (b0.x + b1.x) + (b2.x + b3.x);
        acc.w += (b0.y + b1.y) + (b2.y + b3.y);
    }
    for (; p < end; p++) {
        int s0 = __ldg(g_esrc + p);
        uint2 u0 = __ldg((const uint2*)(g_xw1h + (size_t)s0 * 128) + lane);
        float2 a0 = __half22float2(*(__half2*)&u0.x), b0 = __half22float2(*(__half2*)&u0.y);
        acc.x += a0.x; acc.y += a0.y; acc.z += b0.x; acc.w += b0.y;
    }

    float si = g_s_in[i];
    float4 b4 = __ldg((const float4*)bg + lane);
    float4 g;
    g.x = 1.f / (1.f + expf(-(acc.x * si + b4.x)));
    g.y = 1.f / (1.f + expf(-(acc.y * si + b4.y)));
    g.z = 1.f / (1.f + expf(-(acc.z * si + b4.z)));
    g.w = 1.f / (1.f + expf(-(acc.w * si + b4.w)));

    if (lane < 16) {
        float4 h4 = __ldg((const float4*)(h + (size_t)i * 64) + lane);
        *((float4*)(g_rh + (size_t)i * 64) + lane) =
            make_float4(g.x * h4.x, g.y * h4.y, g.z * h4.z, g.w * h4.w);
    } else {
        *((float4*)(g_z + (size_t)i * 64) + (lane - 16)) = g;
    }
}

// ---------------------------------------------------------------------------
// GEMM2: xw2[N,64] = diag(s_out)*[x|rh] @ Wc[128,64]  (fp16 out)
// ---------------------------------------------------------------------------
__global__ __launch_bounds__(256, 2) void k_gemm2(
    const float* __restrict__ x, const float* __restrict__ Wc, int n)
{
    __shared__ float Asm[16][132];
    __shared__ float Wsm[16][64];
    int t = threadIdx.x;
    int row0 = blockIdx.x * 128;
    int tr = t >> 3, tc = t & 7;

    float acc0[4][4], acc1[4][4];
#pragma unroll
    for (int i = 0; i < 4; i++)
#pragma unroll
        for (int j = 0; j < 4; j++) { acc0[i][j] = 0.f; acc1[i][j] = 0.f; }

    for (int k0 = 0; k0 < 128; k0 += 16) {
#pragma unroll
        for (int half = 0; half < 2; half++) {
            int q = t + half * 256;
            int m = q >> 2, kq = q & 3;
            int gr = row0 + m;
            float4 v = make_float4(0.f, 0.f, 0.f, 0.f);
            if (gr < n) {
                int kk = k0 + kq * 4;
                const float* src = (kk < 64) ? (x + (size_t)gr * 64 + kk)
                                             : (g_rh + (size_t)gr * 64 + kk - 64);
                v = *(const float4*)src;
                float s = g_s_out[gr];
                v.x *= s; v.y *= s; v.z *= s; v.w *= s;
            }
            Asm[kq * 4 + 0][m] = v.x;
            Asm[kq * 4 + 1][m] = v.y;
            Asm[kq * 4 + 2][m] = v.z;
            Asm[kq * 4 + 3][m] = v.w;
        }
        {
            int k = t >> 4, c4 = t & 15;
            *(float4*)(&Wsm[k][c4 * 4]) =
                *(const float4*)(Wc + (size_t)(k0 + k) * 64 + c4 * 4);
        }
        __syncthreads();

#pragma unroll
        for (int kk = 0; kk < 16; kk++) {
            float4 av = *(const float4*)(&Asm[kk][tr * 4]);
            float4 w0 = *(const float4*)(&Wsm[kk][tc * 4]);
            float4 w1 = *(const float4*)(&Wsm[kk][32 + tc * 4]);
            float a[4] = {av.x, av.y, av.z, av.w};
            float wa[4] = {w0.x, w0.y, w0.z, w0.w};
            float wb[4] = {w1.x, w1.y, w1.z, w1.w};
#pragma unroll
            for (int i = 0; i < 4; i++)
#pragma unroll
                for (int j = 0; j < 4; j++) {
                    acc0[i][j] += a[i] * wa[j];
                    acc1[i][j] += a[i] * wb[j];
                }
        }
        __syncthreads();
    }

#pragma unroll
    for (int i = 0; i < 4; i++) {
        int gr = row0 + tr * 4 + i;
        if (gr < n) {
            __half2 p0 = __floats2half2_rn(acc0[i][0], acc0[i][1]);
            __half2 p1 = __floats2half2_rn(acc0[i][2], acc0[i][3]);
            __half2 p2 = __floats2half2_rn(acc1[i][0], acc1[i][1]);
            __half2 p3 = __floats2half2_rn(acc1[i][2], acc1[i][3]);
            *(uint2*)(g_xw2h + (size_t)gr * 64 + tc * 4) =
                make_uint2(*(unsigned*)&p0, *(unsigned*)&p1);
            *(uint2*)(g_xw2h + (size_t)gr * 64 + 32 + tc * 4) =
                make_uint2(*(unsigned*)&p2, *(unsigned*)&p3);
        }
    }
}

// ---------------------------------------------------------------------------
// Agg2 + GRU epilogue fused: 16 lanes per node (fp16 gathers)
// ---------------------------------------------------------------------------
__global__ __launch_bounds__(256) void k_agg2_final(
    const float* __restrict__ h, const float* __restrict__ bc,
    float* __restrict__ out, int n)
{
    int gt = blockIdx.x * blockDim.x + threadIdx.x;
    int i = gt >> 4;
    if (i >= n) return;
    int q = gt & 15;

    int p   = g_row[i];
    int end = g_row[i + 1];
    float4 acc = make_float4(0.f, 0.f, 0.f, 0.f);
    for (; p + 4 <= end; p += 4) {
        int s0 = __ldg(g_esrc + p);
        int s1 = __ldg(g_esrc + p + 1);
        int s2 = __ldg(g_esrc + p + 2);
        int s3 = __ldg(g_esrc + p + 3);
        uint2 u0 = __ldg((const uint2*)(g_xw2h + (size_t)s0 * 64) + q);
        uint2 u1 = __ldg((const uint2*)(g_xw2h + (size_t)s1 * 64) + q);
        uint2 u2 = __ldg((const uint2*)(g_xw2h + (size_t)s2 * 64) + q);
        uint2 u3 = __ldg((const uint2*)(g_xw2h + (size_t)s3 * 64) + q);
        float2 a0 = __half22float2(*(__half2*)&u0.x), b0 = __half22float2(*(__half2*)&u0.y);
        float2 a1 = __half22float2(*(__half2*)&u1.x), b1 = __half22float2(*(__half2*)&u1.y);
        float2 a2 = __half22float2(*(__half2*)&u2.x), b2 = __half22float2(*(__half2*)&u2.y);
        float2 a3 = __half22float2(*(__half2*)&u3.x), b3 = __half22float2(*(__half2*)&u3.y);
        acc.x += (a0.x + a1.x) + (a2.x + a3.x);
        acc.y += (a0.y + a1.y) + (a2.y + a3.y);
        acc.z += (b0.x + b1.x) + (b2.x + b3.x);
        acc.w += (b0.y + b1.y) + (b2.y + b3.y);
    }
    for (; p < end; p++) {
        int s0 = __ldg(g_esrc + p);
        uint2 u0 = __ldg((const uint2*)(g_xw2h + (size_t)s0 * 64) + q);
        float2 a0 = __half22float2(*(__half2*)&u0.x), b0 = __half22float2(*(__half2*)&u0.y);
        acc.x += a0.x; acc.y += a0.y; acc.z += b0.x; acc.w += b0.y;
    }

    float si = g_s_in[i];
    float4 b4 = __ldg((const float4*)bc + q);
    float4 z4 = *((const float4*)(g_z + (size_t)i * 64) + q);
    float4 h4 = __ldg((const float4*)(h + (size_t)i * 64) + q);
    float4 o;
    o.x = z4.x * h4.x + (1.f - z4.x) * tanhf(acc.x * si + b4.x);
    o.y = z4.y * h4.y + (1.f - z4.y) * tanhf(acc.y * si + b4.y);
    o.z = z4.z * h4.z + (1.f - z4.z) * tanhf(acc.z * si + b4.z);
    o.w = z4.w * h4.w + (1.f - z4.w) * tanhf(acc.w * si + b4.w);
    *((float4*)(out + (size_t)i * 64) + q) = o;
}

// ---------------------------------------------------------------------------
extern "C" void kernel_launch(void* const* d_in, const int* in_sizes, int n_in,
                              void* d_out, int out_size)
{
    const float* x   = (const float*)d_in[0];
    const float* h   = (const float*)d_in[1];
    const int*   src = (const int*)  d_in[2];
    const int*   dst = (const int*)  d_in[3];
    const float* Wg  = (const float*)d_in[4];
    const float* bg  = (const float*)d_in[5];
    const float* Wc  = (const float*)d_in[6];
    const float* bc  = (const float*)d_in[7];
    float* out = (float*)d_out;

    int n = in_sizes[0] / 64;
    int E = in_sizes[2];
    int NB = (n + 1023) / 1024;

    int nb;
    nb = (n + 255) / 256;              k_zero   <<<nb, 256>>>(n);
    nb = (E + 255) / 256;              k_degree <<<nb, 256>>>(src, dst, E);

    k_scan1<<<NB, 1024>>>(n);
    k_scan2<<<1, 128>>>(NB, n);
    k_scan3<<<NB, 1024>>>(n);
    nb = (E + 255) / 256;              k_bucket <<<nb, 256>>>(src, dst, E);

    int tiles = (n + 127) / 128;
    k_gemm1<<<tiles, 256>>>(x, h, Wg, n);

    nb = (int)(((long long)n * 32 + 255) / 256);
    k_agg1_gates<<<nb, 256>>>(h, bg, n);

    k_gemm2<<<tiles, 256>>>(x, Wc, n);

    nb = (int)(((long long)n * 16 + 255) / 256);
    k_agg2_final<<<nb, 256>>>(h, bc, out, n);
}

// round 8
// speedup vs baseline: 2.6077x; 1.0780x over previous
#include <cuda_runtime.h>
#include <cuda_fp16.h>
#include <math.h>
#include <stdint.h>

#define NMAX 100000
#define EMAX 2000000

// Scratch (allocation-free rule: __device__ globals)
__device__ int    g_deg_in [NMAX];
__device__ int    g_deg_out[NMAX];
__device__ float  g_s_out[NMAX];
__device__ float  g_s_in [NMAX];
__device__ int    g_row   [NMAX + 1];
__device__ int    g_cursor[NMAX];
__device__ int    g_bsum  [128];
__device__ int    g_esrc  [EMAX];
__device__ __half g_xw1h[(size_t)NMAX * 128];
__device__ __half g_xw2h[(size_t)NMAX * 64];
__device__ float  g_z   [(size_t)NMAX * 64];
__device__ float  g_rh  [(size_t)NMAX * 64];

// ---------------------------------------------------------------------------
__global__ void k_zero(int n) {
    int i = blockIdx.x * blockDim.x + threadIdx.x;
    if (i < n) { g_deg_in[i] = 0; g_deg_out[i] = 0; }
}

__global__ void k_degree(const int* __restrict__ src, const int* __restrict__ dst, int E) {
    int e = blockIdx.x * blockDim.x + threadIdx.x;
    if (e < E) {
        atomicAdd(&g_deg_out[src[e]], 1);
        atomicAdd(&g_deg_in [dst[e]], 1);
    }
}

// ---------------------------------------------------------------------------
// Prefix scan of deg_in -> g_row (exclusive), g_cursor = g_row; also rsqrt
// ---------------------------------------------------------------------------
__global__ __launch_bounds__(1024) void k_scan1(int n) {
    int t = threadIdx.x;
    int i = blockIdx.x * 1024 + t;
    int v = (i < n) ? g_deg_in[i] : 0;
    for (int o = 16; o > 0; o >>= 1) v += __shfl_down_sync(~0u, v, o);
    __shared__ int ws[32];
    if ((t & 31) == 0) ws[t >> 5] = v;
    __syncthreads();
    if (t < 32) {
        int u = ws[t];
        for (int o = 16; o > 0; o >>= 1) u += __shfl_down_sync(~0u, u, o);
        if (t == 0) g_bsum[blockIdx.x] = u;
    }
}

__global__ void k_scan2(int nb, int n) {
    int t = threadIdx.x;   // 128 threads
    __shared__ int s[128];
    int v = (t < nb) ? g_bsum[t] : 0;
    s[t] = v;
    __syncthreads();
    for (int o = 1; o < 128; o <<= 1) {
        int u = (t >= o) ? s[t - o] : 0;
        __syncthreads();
        s[t] += u;
        __syncthreads();
    }
    if (t < nb) g_bsum[t] = s[t] - v;
    if (t == nb - 1) g_row[n] = s[t];
}

__global__ __launch_bounds__(1024) void k_scan3(int n) {
    int t = threadIdx.x;
    int i = blockIdx.x * 1024 + t;
    int v = (i < n) ? g_deg_in[i] : 0;
    int lane = t & 31, wid = t >> 5;
    int inc = v;
    for (int o = 1; o < 32; o <<= 1) {
        int u = __shfl_up_sync(~0u, inc, o);
        if (lane >= o) inc += u;
    }
    __shared__ int ws[32];
    if (lane == 31) ws[wid] = inc;
    __syncthreads();
    if (t < 32) {
        int u = ws[t];
        for (int o = 1; o < 32; o <<= 1) {
            int w = __shfl_up_sync(~0u, u, o);
            if (t >= o) u += w;
        }
        ws[t] = u;
    }
    __syncthreads();
    int excl = inc - v + (wid > 0 ? ws[wid - 1] : 0) + g_bsum[blockIdx.x];
    if (i < n) {
        g_row[i] = excl;
        g_cursor[i] = excl;
        g_s_in [i] = rsqrtf(fmaxf((float)v, 1.f));
        g_s_out[i] = rsqrtf(fmaxf((float)g_deg_out[i], 1.f));
    }
}

__global__ void k_bucket(const int* __restrict__ src, const int* __restrict__ dst, int E) {
    int e = blockIdx.x * blockDim.x + threadIdx.x;
    if (e < E) {
        int p = atomicAdd(&g_cursor[dst[e]], 1);
        g_esrc[p] = src[e];
    }
}

// ---------------------------------------------------------------------------
// HMMA helper
// ---------------------------------------------------------------------------
__device__ __forceinline__ void mma16816(float* c, const uint32_t* a,
                                         uint32_t b0, uint32_t b1) {
    asm volatile(
        "mma.sync.aligned.m16n8k16.row.col.f32.f16.f16.f32 "
        "{%0,%1,%2,%3}, {%4,%5,%6,%7}, {%8,%9}, {%0,%1,%2,%3};\n"
        : "+f"(c[0]), "+f"(c[1]), "+f"(c[2]), "+f"(c[3])
        : "r"(a[0]), "r"(a[1]), "r"(a[2]), "r"(a[3]), "r"(b0), "r"(b1));
}

// ---------------------------------------------------------------------------
// GEMM1 (HMMA): xw1[N,128] = diag(s_out)*[x|h] @ Wg[128,128]  (fp16 out)
// CTA 128x128, K=128 resident. 8 warps: 4(M) x 2(N), warp tile 32x64.
// smem: Ash[128][136] half + Wsh[n=128][k=136] half (transposed W)
// ---------------------------------------------------------------------------
#define G1_SMEM_BYTES ((128*136 + 128*136) * 2)

__global__ __launch_bounds__(256) void k_gemm1(
    const float* __restrict__ x, const float* __restrict__ h,
    const float* __restrict__ Wg, int n)
{
    extern __shared__ __half sh[];
    __half* Ash = sh;                 // [128][136]
    __half* Wsh = sh + 128 * 136;     // [128][136]  (row = n, col = k)
    int t = threadIdx.x;
    int row0 = blockIdx.x * 128;

    // A tile: 128 rows x 32 float4, scaled fp16
    for (int it = t; it < 128 * 32; it += 256) {
        int m = it >> 5, q = it & 31;
        int gr = row0 + m;
        float4 v = make_float4(0.f, 0.f, 0.f, 0.f);
        if (gr < n) {
            const float* src = (q < 16) ? (x + (size_t)gr * 64 + q * 4)
                                        : (h + (size_t)gr * 64 + (q - 16) * 4);
            v = *(const float4*)src;
            float s = g_s_out[gr];
            v.x *= s; v.y *= s; v.z *= s; v.w *= s;
        }
        __half2 p0 = __floats2half2_rn(v.x, v.y);
        __half2 p1 = __floats2half2_rn(v.z, v.w);
        *(uint2*)(Ash + m * 136 + q * 4) = make_uint2(*(unsigned*)&p0, *(unsigned*)&p1);
    }
    // W transpose load: Wsh[n][k] = Wg[k][n]
    for (int it = t; it < 128 * 32; it += 256) {
        int k = it >> 5, q = it & 31;
        float4 v = *(const float4*)(Wg + (size_t)k * 128 + q * 4);
        Wsh[(q * 4 + 0) * 136 + k] = __float2half(v.x);
        Wsh[(q * 4 + 1) * 136 + k] = __float2half(v.y);
        Wsh[(q * 4 + 2) * 136 + k] = __float2half(v.z);
        Wsh[(q * 4 + 3) * 136 + k] = __float2half(v.w);
    }
    __syncthreads();

    int wid = t >> 5, lane = t & 31;
    int gp = lane >> 2, tg = lane & 3;
    int wm = (wid >> 1) * 32, wn = (wid & 1) * 64;

    float acc[2][8][4];
#pragma unroll
    for (int mi = 0; mi < 2; mi++)
#pragma unroll
        for (int ni = 0; ni < 8; ni++)
#pragma unroll
            for (int j = 0; j < 4; j++) acc[mi][ni][j] = 0.f;

#pragma unroll
    for (int k0 = 0; k0 < 128; k0 += 16) {
        uint32_t a[2][4];
#pragma unroll
        for (int mi = 0; mi < 2; mi++) {
            int r = wm + mi * 16 + gp;
            a[mi][0] = *(uint32_t*)(Ash + r * 136 + k0 + tg * 2);
            a[mi][1] = *(uint32_t*)(Ash + (r + 8) * 136 + k0 + tg * 2);
            a[mi][2] = *(uint32_t*)(Ash + r * 136 + k0 + 8 + tg * 2);
            a[mi][3] = *(uint32_t*)(Ash + (r + 8) * 136 + k0 + 8 + tg * 2);
        }
#pragma unroll
        for (int ni = 0; ni < 8; ni++) {
            int c = wn + ni * 8 + gp;
            uint32_t b0 = *(uint32_t*)(Wsh + c * 136 + k0 + tg * 2);
            uint32_t b1 = *(uint32_t*)(Wsh + c * 136 + k0 + 8 + tg * 2);
            mma16816(acc[0][ni], a[0], b0, b1);
            mma16816(acc[1][ni], a[1], b0, b1);
        }
    }

#pragma unroll
    for (int mi = 0; mi < 2; mi++) {
        int r = row0 + wm + mi * 16 + gp;
#pragma unroll
        for (int ni = 0; ni < 8; ni++) {
            int c = wn + ni * 8 + tg * 2;
            if (r < n) {
                __half2 p = __floats2half2_rn(acc[mi][ni][0], acc[mi][ni][1]);
                *(unsigned*)(g_xw1h + (size_t)r * 128 + c) = *(unsigned*)&p;
            }
            if (r + 8 < n) {
                __half2 p = __floats2half2_rn(acc[mi][ni][2], acc[mi][ni][3]);
                *(unsigned*)(g_xw1h + (size_t)(r + 8) * 128 + c) = *(unsigned*)&p;
            }
        }
    }
}

// ---------------------------------------------------------------------------
// Agg1 + gates fused: warp per node (fp16 gathers, fp32 accum)
// ---------------------------------------------------------------------------
__global__ __launch_bounds__(256) void k_agg1_gates(
    const float* __restrict__ h, const float* __restrict__ bg, int n)
{
    int gt = blockIdx.x * blockDim.x + threadIdx.x;
    int i = gt >> 5;
    if (i >= n) return;
    int lane = gt & 31;

    int p   = g_row[i];
    int end = g_row[i + 1];
    float4 acc = make_float4(0.f, 0.f, 0.f, 0.f);
    for (; p + 4 <= end; p += 4) {
        int s0 = __ldg(g_esrc + p);
        int s1 = __ldg(g_esrc + p + 1);
        int s2 = __ldg(g_esrc + p + 2);
        int s3 = __ldg(g_esrc + p + 3);
        uint2 u0 = __ldg((const uint2*)(g_xw1h + (size_t)s0 * 128) + lane);
        uint2 u1 = __ldg((const uint2*)(g_xw1h + (size_t)s1 * 128) + lane);
        uint2 u2 = __ldg((const uint2*)(g_xw1h + (size_t)s2 * 128) + lane);
        uint2 u3 = __ldg((const uint2*)(g_xw1h + (size_t)s3 * 128) + lane);
        float2 a0 = __half22float2(*(__half2*)&u0.x), b0 = __half22float2(*(__half2*)&u0.y);
        float2 a1 = __half22float2(*(__half2*)&u1.x), b1 = __half22float2(*(__half2*)&u1.y);
        float2 a2 = __half22float2(*(__half2*)&u2.x), b2 = __half22float2(*(__half2*)&u2.y);
        float2 a3 = __half22float2(*(__half2*)&u3.x), b3 = __half22float2(*(__half2*)&u3.y);
        acc.x += (a0.x + a1.x) + (a2.x + a3.x);
        acc.y += (a0.y + a1.y) + (a2.y + a3.y);
        acc.z += (b0.x + b1.x) + (b2.x + b3.x);
        acc.w += (b0.y + b1.y) + (b2.y + b3.y);
    }
    for (; p < end; p++) {
        int s0 = __ldg(g_esrc + p);
        uint2 u0 = __ldg((const uint2*)(g_xw1h + (size_t)s0 * 128) + lane);
        float2 a0 = __half22float2(*(__half2*)&u0.x), b0 = __half22float2(*(__half2*)&u0.y);
        acc.x += a0.x; acc.y += a0.y; acc.z += b0.x; acc.w += b0.y;
    }

    float si = g_s_in[i];
    float4 b4 = __ldg((const float4*)bg + lane);
    float4 g;
    g.x = 1.f / (1.f + expf(-(acc.x * si + b4.x)));
    g.y = 1.f / (1.f + expf(-(acc.y * si + b4.y)));
    g.z = 1.f / (1.f + expf(-(acc.z * si + b4.z)));
    g.w = 1.f / (1.f + expf(-(acc.w * si + b4.w)));

    if (lane < 16) {
        float4 h4 = __ldg((const float4*)(h + (size_t)i * 64) + lane);
        *((float4*)(g_rh + (size_t)i * 64) + lane) =
            make_float4(g.x * h4.x, g.y * h4.y, g.z * h4.z, g.w * h4.w);
    } else {
        *((float4*)(g_z + (size_t)i * 64) + (lane - 16)) = g;
    }
}

// ---------------------------------------------------------------------------
// GEMM2 (HMMA): xw2[N,64] = diag(s_out)*[x|rh] @ Wc[128,64]  (fp16 out)
// CTA 128x64, 8 warps stacked in M, warp tile 16x64.
// smem: Ash[128][136] + Wsh[n=64][k=136]
// ---------------------------------------------------------------------------
#define G2_SMEM_BYTES ((128*136 + 64*136) * 2)

__global__ __launch_bounds__(256) void k_gemm2(
    const float* __restrict__ x, const float* __restrict__ Wc, int n)
{
    extern __shared__ __half sh[];
    __half* Ash = sh;               // [128][136]
    __half* Wsh = sh + 128 * 136;   // [64][136]
    int t = threadIdx.x;
    int row0 = blockIdx.x * 128;

    for (int it = t; it < 128 * 32; it += 256) {
        int m = it >> 5, q = it & 31;
        int gr = row0 + m;
        float4 v = make_float4(0.f, 0.f, 0.f, 0.f);
        if (gr < n) {
            const float* src = (q < 16) ? (x + (size_t)gr * 64 + q * 4)
                                        : (g_rh + (size_t)gr * 64 + (q - 16) * 4);
            v = *(const float4*)src;
            float s = g_s_out[gr];
            v.x *= s; v.y *= s; v.z *= s; v.w *= s;
        }
        __half2 p0 = __floats2half2_rn(v.x, v.y);
        __half2 p1 = __floats2half2_rn(v.z, v.w);
        *(uint2*)(Ash + m * 136 + q * 4) = make_uint2(*(unsigned*)&p0, *(unsigned*)&p1);
    }
    // W transpose: Wsh[n][k] = Wc[k][n], Wc is [128][64]
    for (int it = t; it < 128 * 16; it += 256) {
        int k = it >> 4, q = it & 15;
        float4 v = *(const float4*)(Wc + (size_t)k * 64 + q * 4);
        Wsh[(q * 4 + 0) * 136 + k] = __float2half(v.x);
        Wsh[(q * 4 + 1) * 136 + k] = __float2half(v.y);
        Wsh[(q * 4 + 2) * 136 + k] = __float2half(v.z);
        Wsh[(q * 4 + 3) * 136 + k] = __float2half(v.w);
    }
    __syncthreads();

    int wid = t >> 5, lane = t & 31;
    int gp = lane >> 2, tg = lane & 3;
    int wm = wid * 16;

    float acc[8][4];
#pragma unroll
    for (int ni = 0; ni < 8; ni++)
#pragma unroll
        for (int j = 0; j < 4; j++) acc[ni][j] = 0.f;

#pragma unroll
    for (int k0 = 0; k0 < 128; k0 += 16) {
        uint32_t a[4];
        int r = wm + gp;
        a[0] = *(uint32_t*)(Ash + r * 136 + k0 + tg * 2);
        a[1] = *(uint32_t*)(Ash + (r + 8) * 136 + k0 + tg * 2);
        a[2] = *(uint32_t*)(Ash + r * 136 + k0 + 8 + tg * 2);
        a[3] = *(uint32_t*)(Ash + (r + 8) * 136 + k0 + 8 + tg * 2);
#pragma unroll
        for (int ni = 0; ni < 8; ni++) {
            int c = ni * 8 + gp;
            uint32_t b0 = *(uint32_t*)(Wsh + c * 136 + k0 + tg * 2);
            uint32_t b1 = *(uint32_t*)(Wsh + c * 136 + k0 + 8 + tg * 2);
            mma16816(acc[ni], a, b0, b1);
        }
    }

    int r = row0 + wm + gp;
#pragma unroll
    for (int ni = 0; ni < 8; ni++) {
        int c = ni * 8 + tg * 2;
        if (r < n) {
            __half2 p = __floats2half2_rn(acc[ni][0], acc[ni][1]);
            *(unsigned*)(g_xw2h + (size_t)r * 64 + c) = *(unsigned*)&p;
        }
        if (r + 8 < n) {
            __half2 p = __floats2half2_rn(acc[ni][2], acc[ni][3]);
            *(unsigned*)(g_xw2h + (size_t)(r + 8) * 64 + c) = *(unsigned*)&p;
        }
    }
}

// ---------------------------------------------------------------------------
// Agg2 + GRU epilogue fused: 16 lanes per node (fp16 gathers)
// ---------------------------------------------------------------------------
__global__ __launch_bounds__(256) void k_agg2_final(
    const float* __restrict__ h, const float* __restrict__ bc,
    float* __restrict__ out, int n)
{
    int gt = blockIdx.x * blockDim.x + threadIdx.x;
    int i = gt >> 4;
    if (i >= n) return;
    int q = gt & 15;

    int p   = g_row[i];
    int end = g_row[i + 1];
    float4 acc = make_float4(0.f, 0.f, 0.f, 0.f);
    for (; p + 4 <= end; p += 4) {
        int s0 = __ldg(g_esrc + p);
        int s1 = __ldg(g_esrc + p + 1);
        int s2 = __ldg(g_esrc + p + 2);
        int s3 = __ldg(g_esrc + p + 3);
        uint2 u0 = __ldg((const uint2*)(g_xw2h + (size_t)s0 * 64) + q);
        uint2 u1 = __ldg((const uint2*)(g_xw2h + (size_t)s1 * 64) + q);
        uint2 u2 = __ldg((const uint2*)(g_xw2h + (size_t)s2 * 64) + q);
        uint2 u3 = __ldg((const uint2*)(g_xw2h + (size_t)s3 * 64) + q);
        float2 a0 = __half22float2(*(__half2*)&u0.x), b0 = __half22float2(*(__half2*)&u0.y);
        float2 a1 = __half22float2(*(__half2*)&u1.x), b1 = __half22float2(*(__half2*)&u1.y);
        float2 a2 = __half22float2(*(__half2*)&u2.x), b2 = __half22float2(*(__half2*)&u2.y);
        float2 a3 = __half22float2(*(__half2*)&u3.x), b3 = __half22float2(*(__half2*)&u3.y);
        acc.x += (a0.x + a1.x) + (a2.x + a3.x);
        acc.y += (a0.y + a1.y) + (a2.y + a3.y);
        acc.z += (b0.x + b1.x) + (b2.x + b3.x);
        acc.w += (b0.y + b1.y) + (b2.y + b3.y);
    }
    for (; p < end; p++) {
        int s0 = __ldg(g_esrc + p);
        uint2 u0 = __ldg((const uint2*)(g_xw2h + (size_t)s0 * 64) + q);
        float2 a0 = __half22float2(*(__half2*)&u0.x), b0 = __half22float2(*(__half2*)&u0.y);
        acc.x += a0.x; acc.y += a0.y; acc.z += b0.x; acc.w += b0.y;
    }

    float si = g_s_in[i];
    float4 b4 = __ldg((const float4*)bc + q);
    float4 z4 = *((const float4*)(g_z + (size_t)i * 64) + q);
    float4 h4 = __ldg((const float4*)(h + (size_t)i * 64) + q);
    float4 o;
    o.x = z4.x * h4.x + (1.f - z4.x) * tanhf(acc.x * si + b4.x);
    o.y = z4.y * h4.y + (1.f - z4.y) * tanhf(acc.y * si + b4.y);
    o.z = z4.z * h4.z + (1.f - z4.z) * tanhf(acc.z * si + b4.z);
    o.w = z4.w * h4.w + (1.f - z4.w) * tanhf(acc.w * si + b4.w);
    *((float4*)(out + (size_t)i * 64) + q) = o;
}

// ---------------------------------------------------------------------------
extern "C" void kernel_launch(void* const* d_in, const int* in_sizes, int n_in,
                              void* d_out, int out_size)
{
    const float* x   = (const float*)d_in[0];
    const float* h   = (const float*)d_in[1];
    const int*   src = (const int*)  d_in[2];
    const int*   dst = (const int*)  d_in[3];
    const float* Wg  = (const float*)d_in[4];
    const float* bg  = (const float*)d_in[5];
    const float* Wc  = (const float*)d_in[6];
    const float* bc  = (const float*)d_in[7];
    float* out = (float*)d_out;

    int n = in_sizes[0] / 64;
    int E = in_sizes[2];
    int NB = (n + 1023) / 1024;

    cudaFuncSetAttribute(k_gemm1, cudaFuncAttributeMaxDynamicSharedMemorySize, G1_SMEM_BYTES);
    cudaFuncSetAttribute(k_gemm2, cudaFuncAttributeMaxDynamicSharedMemorySize, G2_SMEM_BYTES);

    int nb;
    nb = (n + 255) / 256;              k_zero   <<<nb, 256>>>(n);
    nb = (E + 255) / 256;              k_degree <<<nb, 256>>>(src, dst, E);

    k_scan1<<<NB, 1024>>>(n);
    k_scan2<<<1, 128>>>(NB, n);
    k_scan3<<<NB, 1024>>>(n);
    nb = (E + 255) / 256;              k_bucket <<<nb, 256>>>(src, dst, E);

    int tiles = (n + 127) / 128;
    k_gemm1<<<tiles, 256, G1_SMEM_BYTES>>>(x, h, Wg, n);

    nb = (int)(((long long)n * 32 + 255) / 256);
    k_agg1_gates<<<nb, 256>>>(h, bg, n);

    k_gemm2<<<tiles, 256, G2_SMEM_BYTES>>>(x, Wc, n);

    nb = (int)(((long long)n * 16 + 255) / 256);
    k_agg2_final<<<nb, 256>>>(h, bc, out, n);
}

// round 10
// speedup vs baseline: 2.7013x; 1.0359x over previous
#include <cuda_runtime.h>
#include <cuda_fp16.h>
#include <math.h>
#include <stdint.h>

#define NMAX 100000
#define EMAX 2000000

// Scratch (allocation-free rule: __device__ globals)
__device__ int    g_deg_in [NMAX];
__device__ int    g_deg_out[NMAX];
__device__ float  g_s_out[NMAX];
__device__ float  g_s_in [NMAX];
__device__ int    g_row   [NMAX + 1];
__device__ int    g_cursor[NMAX];
__device__ int    g_esrc  [EMAX];
__device__ int    g_blk_agg [128];
__device__ int    g_blk_flag[128];
__device__ __half g_xw1h[(size_t)NMAX * 128];
__device__ __half g_xw2h[(size_t)NMAX * 64];
__device__ float  g_z   [(size_t)NMAX * 64];
__device__ float  g_rh  [(size_t)NMAX * 64];

// ---------------------------------------------------------------------------
__global__ void k_zero(int n) {
    int i = blockIdx.x * blockDim.x + threadIdx.x;
    if (i < n) { g_deg_in[i] = 0; g_deg_out[i] = 0; }
    if (i < 128) g_blk_flag[i] = 0;
}

__global__ void k_degree(const int* __restrict__ src, const int* __restrict__ dst, int E) {
    int e = blockIdx.x * blockDim.x + threadIdx.x;
    if (e < E) {
        atomicAdd(&g_deg_out[src[e]], 1);
        atomicAdd(&g_deg_in [dst[e]], 1);
    }
}

// ---------------------------------------------------------------------------
// Single-pass scan (decoupled lookback): row/cursor/s_in/s_out in one kernel.
// 1024 threads/block, <=98 blocks (all co-resident -> spin is safe).
// ---------------------------------------------------------------------------
__global__ __launch_bounds__(1024) void k_scan(int n) {
    int b = blockIdx.x, t = threadIdx.x;
    int i = b * 1024 + t;
    int v = (i < n) ? g_deg_in[i] : 0;
    int lane = t & 31, wid = t >> 5;

    // block-wide inclusive scan
    int inc = v;
    for (int o = 1; o < 32; o <<= 1) {
        int u = __shfl_up_sync(~0u, inc, o);
        if (lane >= o) inc += u;
    }
    __shared__ int ws[32];
    if (lane == 31) ws[wid] = inc;
    __syncthreads();
    if (t < 32) {
        int u = ws[t];
        for (int o = 1; o < 32; o <<= 1) {
            int w = __shfl_up_sync(~0u, u, o);
            if (t >= o) u += w;
        }
        ws[t] = u;
    }
    __syncthreads();
    int block_incl = inc + (wid ? ws[wid - 1] : 0);
    int total = ws[31];

    // publish aggregate
    if (t == 0) {
        g_blk_agg[b] = total;
        __threadfence();
        *((volatile int*)&g_blk_flag[b]) = 1;
    }

    // lookback (warp 0, strided over predecessors)
    __shared__ int s_prefix;
    if (wid == 0) {
        int sum = 0;
        for (int p = lane; p < b; p += 32) {
            while (*((volatile int*)&g_blk_flag[p]) == 0) { }
            sum += *((volatile int*)&g_blk_agg[p]);
        }
        for (int o = 16; o > 0; o >>= 1) sum += __shfl_down_sync(~0u, sum, o);
        if (lane == 0) s_prefix = sum;
    }
    __syncthreads();

    int excl = s_prefix + block_incl - v;
    if (i < n) {
        g_row[i]    = excl;
        g_cursor[i] = excl;
        g_s_in [i]  = rsqrtf(fmaxf((float)v, 1.f));
        g_s_out[i]  = rsqrtf(fmaxf((float)g_deg_out[i], 1.f));
        if (i == n - 1) g_row[n] = excl + v;
    }
}

// ---------------------------------------------------------------------------
// HMMA helper
// ---------------------------------------------------------------------------
__device__ __forceinline__ void mma16816(float* c, const uint32_t* a,
                                         uint32_t b0, uint32_t b1) {
    asm volatile(
        "mma.sync.aligned.m16n8k16.row.col.f32.f16.f16.f32 "
        "{%0,%1,%2,%3}, {%4,%5,%6,%7}, {%8,%9}, {%0,%1,%2,%3};\n"
        : "+f"(c[0]), "+f"(c[1]), "+f"(c[2]), "+f"(c[3])
        : "r"(a[0]), "r"(a[1]), "r"(a[2]), "r"(a[3]), "r"(b0), "r"(b1));
}

// ---------------------------------------------------------------------------
// Fused GEMM1 (HMMA) + bucket scatter.
// Blocks [0, tiles): xw1[N,128] = diag(s_out)*[x|h] @ Wg  (fp16 out)
// Blocks [tiles, tiles+bucketB): counting-sort edge scatter (independent work)
// ---------------------------------------------------------------------------
#define G1_SMEM_BYTES ((128*136 + 128*136) * 2)

__global__ __launch_bounds__(256) void k_gemm1_bucket(
    const float* __restrict__ x, const float* __restrict__ h,
    const float* __restrict__ Wg,
    const int* __restrict__ src, const int* __restrict__ dst,
    int n, int E, int tiles)
{
    if (blockIdx.x >= tiles) {
        // ---- bucket part ----
        int e = (blockIdx.x - tiles) * 256 + threadIdx.x;
        if (e < E) {
            int p = atomicAdd(&g_cursor[dst[e]], 1);
            g_esrc[p] = src[e];
        }
        return;
    }

    // ---- GEMM part ----
    extern __shared__ __half sh[];
    __half* Ash = sh;                 // [128][136]
    __half* Wsh = sh + 128 * 136;     // [128][136]  (row = n, col = k)
    int t = threadIdx.x;
    int row0 = blockIdx.x * 128;

    for (int it = t; it < 128 * 32; it += 256) {
        int m = it >> 5, q = it & 31;
        int gr = row0 + m;
        float4 v = make_float4(0.f, 0.f, 0.f, 0.f);
        if (gr < n) {
            const float* srcp = (q < 16) ? (x + (size_t)gr * 64 + q * 4)
                                         : (h + (size_t)gr * 64 + (q - 16) * 4);
            v = *(const float4*)srcp;
            float s = g_s_out[gr];
            v.x *= s; v.y *= s; v.z *= s; v.w *= s;
        }
        __half2 p0 = __floats2half2_rn(v.x, v.y);
        __half2 p1 = __floats2half2_rn(v.z, v.w);
        *(uint2*)(Ash + m * 136 + q * 4) = make_uint2(*(unsigned*)&p0, *(unsigned*)&p1);
    }
    for (int it = t; it < 128 * 32; it += 256) {
        int k = it >> 5, q = it & 31;
        float4 v = *(const float4*)(Wg + (size_t)k * 128 + q * 4);
        Wsh[(q * 4 + 0) * 136 + k] = __float2half(v.x);
        Wsh[(q * 4 + 1) * 136 + k] = __float2half(v.y);
        Wsh[(q * 4 + 2) * 136 + k] = __float2half(v.z);
        Wsh[(q * 4 + 3) * 136 + k] = __float2half(v.w);
    }
    __syncthreads();

    int wid = t >> 5, lane = t & 31;
    int gp = lane >> 2, tg = lane & 3;
    int wm = (wid >> 1) * 32, wn = (wid & 1) * 64;

    float acc[2][8][4];
#pragma unroll
    for (int mi = 0; mi < 2; mi++)
#pragma unroll
        for (int ni = 0; ni < 8; ni++)
#pragma unroll
            for (int j = 0; j < 4; j++) acc[mi][ni][j] = 0.f;

#pragma unroll
    for (int k0 = 0; k0 < 128; k0 += 16) {
        uint32_t a[2][4];
#pragma unroll
        for (int mi = 0; mi < 2; mi++) {
            int r = wm + mi * 16 + gp;
            a[mi][0] = *(uint32_t*)(Ash + r * 136 + k0 + tg * 2);
            a[mi][1] = *(uint32_t*)(Ash + (r + 8) * 136 + k0 + tg * 2);
            a[mi][2] = *(uint32_t*)(Ash + r * 136 + k0 + 8 + tg * 2);
            a[mi][3] = *(uint32_t*)(Ash + (r + 8) * 136 + k0 + 8 + tg * 2);
        }
#pragma unroll
        for (int ni = 0; ni < 8; ni++) {
            int c = wn + ni * 8 + gp;
            uint32_t b0 = *(uint32_t*)(Wsh + c * 136 + k0 + tg * 2);
            uint32_t b1 = *(uint32_t*)(Wsh + c * 136 + k0 + 8 + tg * 2);
            mma16816(acc[0][ni], a[0], b0, b1);
            mma16816(acc[1][ni], a[1], b0, b1);
        }
    }

#pragma unroll
    for (int mi = 0; mi < 2; mi++) {
        int r = row0 + wm + mi * 16 + gp;
#pragma unroll
        for (int ni = 0; ni < 8; ni++) {
            int c = wn + ni * 8 + tg * 2;
            if (r < n) {
                __half2 p = __floats2half2_rn(acc[mi][ni][0], acc[mi][ni][1]);
                *(unsigned*)(g_xw1h + (size_t)r * 128 + c) = *(unsigned*)&p;
            }
            if (r + 8 < n) {
                __half2 p = __floats2half2_rn(acc[mi][ni][2], acc[mi][ni][3]);
                *(unsigned*)(g_xw1h + (size_t)(r + 8) * 128 + c) = *(unsigned*)&p;
            }
        }
    }
}

// ---------------------------------------------------------------------------
// Agg1 + gates fused: warp per node, 8-deep gather unroll for MLP
// ---------------------------------------------------------------------------
__global__ __launch_bounds__(256) void k_agg1_gates(
    const float* __restrict__ h, const float* __restrict__ bg, int n)
{
    int gt = blockIdx.x * blockDim.x + threadIdx.x;
    int i = gt >> 5;
    if (i >= n) return;
    int lane = gt & 31;

    int p   = g_row[i];
    int end = g_row[i + 1];
    float4 acc = make_float4(0.f, 0.f, 0.f, 0.f);

    for (; p + 8 <= end; p += 8) {
        int s[8];
#pragma unroll
        for (int j = 0; j < 8; j++) s[j] = __ldg(g_esrc + p + j);
        uint2 u[8];
#pragma unroll
        for (int j = 0; j < 8; j++)
            u[j] = __ldg((const uint2*)(g_xw1h + (size_t)s[j] * 128) + lane);
#pragma unroll
        for (int j = 0; j < 8; j++) {
            float2 a = __half22float2(*(__half2*)&u[j].x);
            float2 b = __half22float2(*(__half2*)&u[j].y);
            acc.x += a.x; acc.y += a.y; acc.z += b.x; acc.w += b.y;
        }
    }
    if (p + 4 <= end) {
        int s[4];
#pragma unroll
        for (int j = 0; j < 4; j++) s[j] = __ldg(g_esrc + p + j);
        uint2 u[4];
#pragma unroll
        for (int j = 0; j < 4; j++)
            u[j] = __ldg((const uint2*)(g_xw1h + (size_t)s[j] * 128) + lane);
#pragma unroll
        for (int j = 0; j < 4; j++) {
            float2 a = __half22float2(*(__half2*)&u[j].x);
            float2 b = __half22float2(*(__half2*)&u[j].y);
            acc.x += a.x; acc.y += a.y; acc.z += b.x; acc.w += b.y;
        }
        p += 4;
    }
    for (; p < end; p++) {
        int s0 = __ldg(g_esrc + p);
        uint2 u0 = __ldg((const uint2*)(g_xw1h + (size_t)s0 * 128) + lane);
        float2 a0 = __half22float2(*(__half2*)&u0.x), b0 = __half22float2(*(__half2*)&u0.y);
        acc.x += a0.x; acc.y += a0.y; acc.z += b0.x; acc.w += b0.y;
    }

    float si = g_s_in[i];
    float4 b4 = __ldg((const float4*)bg + lane);
    float4 g;
    g.x = 1.f / (1.f + expf(-(acc.x * si + b4.x)));
    g.y = 1.f / (1.f + expf(-(acc.y * si + b4.y)));
    g.z = 1.f / (1.f + expf(-(acc.z * si + b4.z)));
    g.w = 1.f / (1.f + expf(-(acc.w * si + b4.w)));

    if (lane < 16) {
        float4 h4 = __ldg((const float4*)(h + (size_t)i * 64) + lane);
        *((float4*)(g_rh + (size_t)i * 64) + lane) =
            make_float4(g.x * h4.x, g.y * h4.y, g.z * h4.z, g.w * h4.w);
    } else {
        *((float4*)(g_z + (size_t)i * 64) + (lane - 16)) = g;
    }
}

// ---------------------------------------------------------------------------
// GEMM2 (HMMA): xw2[N,64] = diag(s_out)*[x|rh] @ Wc[128,64]  (fp16 out)
// ---------------------------------------------------------------------------
#define G2_SMEM_BYTES ((128*136 + 64*136) * 2)

__global__ __launch_bounds__(256) void k_gemm2(
    const float* __restrict__ x, const float* __restrict__ Wc, int n)
{
    extern __shared__ __half sh[];
    __half* Ash = sh;               // [128][136]
    __half* Wsh = sh + 128 * 136;   // [64][136]
    int t = threadIdx.x;
    int row0 = blockIdx.x * 128;

    for (int it = t; it < 128 * 32; it += 256) {
        int m = it >> 5, q = it & 31;
        int gr = row0 + m;
        float4 v = make_float4(0.f, 0.f, 0.f, 0.f);
        if (gr < n) {
            const float* srcp = (q < 16) ? (x + (size_t)gr * 64 + q * 4)
                                         : (g_rh + (size_t)gr * 64 + (q - 16) * 4);
            v = *(const float4*)srcp;
            float s = g_s_out[gr];
            v.x *= s; v.y *= s; v.z *= s; v.w *= s;
        }
        __half2 p0 = __floats2half2_rn(v.x, v.y);
        __half2 p1 = __floats2half2_rn(v.z, v.w);
        *(uint2*)(Ash + m * 136 + q * 4) = make_uint2(*(unsigned*)&p0, *(unsigned*)&p1);
    }
    for (int it = t; it < 128 * 16; it += 256) {
        int k = it >> 4, q = it & 15;
        float4 v = *(const float4*)(Wc + (size_t)k * 64 + q * 4);
        Wsh[(q * 4 + 0) * 136 + k] = __float2half(v.x);
        Wsh[(q * 4 + 1) * 136 + k] = __float2half(v.y);
        Wsh[(q * 4 + 2) * 136 + k] = __float2half(v.z);
        Wsh[(q * 4 + 3) * 136 + k] = __float2half(v.w);
    }
    __syncthreads();

    int wid = t >> 5, lane = t & 31;
    int gp = lane >> 2, tg = lane & 3;
    int wm = wid * 16;

    float acc[8][4];
#pragma unroll
    for (int ni = 0; ni < 8; ni++)
#pragma unroll
        for (int j = 0; j < 4; j++) acc[ni][j] = 0.f;

#pragma unroll
    for (int k0 = 0; k0 < 128; k0 += 16) {
        uint32_t a[4];
        int r = wm + gp;
        a[0] = *(uint32_t*)(Ash + r * 136 + k0 + tg * 2);
        a[1] = *(uint32_t*)(Ash + (r + 8) * 136 + k0 + tg * 2);
        a[2] = *(uint32_t*)(Ash + r * 136 + k0 + 8 + tg * 2);
        a[3] = *(uint32_t*)(Ash + (r + 8) * 136 + k0 + 8 + tg * 2);
#pragma unroll
        for (int ni = 0; ni < 8; ni++) {
            int c = ni * 8 + gp;
            uint32_t b0 = *(uint32_t*)(Wsh + c * 136 + k0 + tg * 2);
            uint32_t b1 = *(uint32_t*)(Wsh + c * 136 + k0 + 8 + tg * 2);
            mma16816(acc[ni], a, b0, b1);
        }
    }

    int r = row0 + wm + gp;
#pragma unroll
    for (int ni = 0; ni < 8; ni++) {
        int c = ni * 8 + tg * 2;
        if (r < n) {
            __half2 p = __floats2half2_rn(acc[ni][0], acc[ni][1]);
            *(unsigned*)(g_xw2h + (size_t)r * 64 + c) = *(unsigned*)&p;
        }
        if (r + 8 < n) {
            __half2 p = __floats2half2_rn(acc[ni][2], acc[ni][3]);
            *(unsigned*)(g_xw2h + (size_t)(r + 8) * 64 + c) = *(unsigned*)&p;
        }
    }
}

// ---------------------------------------------------------------------------
// Agg2 + GRU epilogue fused: 16 lanes per node, 8-deep gather unroll
// ---------------------------------------------------------------------------
__global__ __launch_bounds__(256) void k_agg2_final(
    const float* __restrict__ h, const float* __restrict__ bc,
    float* __restrict__ out, int n)
{
    int gt = blockIdx.x * blockDim.x + threadIdx.x;
    int i = gt >> 4;
    if (i >= n) return;
    int q = gt & 15;

    int p   = g_row[i];
    int end = g_row[i + 1];
    float4 acc = make_float4(0.f, 0.f, 0.f, 0.f);

    for (; p + 8 <= end; p += 8) {
        int s[8];
#pragma unroll
        for (int j = 0; j < 8; j++) s[j] = __ldg(g_esrc + p + j);
        uint2 u[8];
#pragma unroll
        for (int j = 0; j < 8; j++)
            u[j] = __ldg((const uint2*)(g_xw2h + (size_t)s[j] * 64) + q);
#pragma unroll
        for (int j = 0; j < 8; j++) {
            float2 a = __half22float2(*(__half2*)&u[j].x);
            float2 b = __half22float2(*(__half2*)&u[j].y);
            acc.x += a.x; acc.y += a.y; acc.z += b.x; acc.w += b.y;
        }
    }
    if (p + 4 <= end) {
        int s[4];
#pragma unroll
        for (int j = 0; j < 4; j++) s[j] = __ldg(g_esrc + p + j);
        uint2 u[4];
#pragma unroll
        for (int j = 0; j < 4; j++)
            u[j] = __ldg((const uint2*)(g_xw2h + (size_t)s[j] * 64) + q);
#pragma unroll
        for (int j = 0; j < 4; j++) {
            float2 a = __half22float2(*(__half2*)&u[j].x);
            float2 b = __half22float2(*(__half2*)&u[j].y);
            acc.x += a.x; acc.y += a.y; acc.z += b.x; acc.w += b.y;
        }
        p += 4;
    }
    for (; p < end; p++) {
        int s0 = __ldg(g_esrc + p);
        uint2 u0 = __ldg((const uint2*)(g_xw2h + (size_t)s0 * 64) + q);
        float2 a0 = __half22float2(*(__half2*)&u0.x), b0 = __half22float2(*(__half2*)&u0.y);
        acc.x += a0.x; acc.y += a0.y; acc.z += b0.x; acc.w += b0.y;
    }

    float si = g_s_in[i];
    float4 b4 = __ldg((const float4*)bc + q);
    float4 z4 = *((const float4*)(g_z + (size_t)i * 64) + q);
    float4 h4 = __ldg((const float4*)(h + (size_t)i * 64) + q);
    float4 o;
    o.x = z4.x * h4.x + (1.f - z4.x) * tanhf(acc.x * si + b4.x);
    o.y = z4.y * h4.y + (1.f - z4.y) * tanhf(acc.y * si + b4.y);
    o.z = z4.z * h4.z + (1.f - z4.z) * tanhf(acc.z * si + b4.z);
    o.w = z4.w * h4.w + (1.f - z4.w) * tanhf(acc.w * si + b4.w);
    *((float4*)(out + (size_t)i * 64) + q) = o;
}

// ---------------------------------------------------------------------------
extern "C" void kernel_launch(void* const* d_in, const int* in_sizes, int n_in,
                              void* d_out, int out_size)
{
    const float* x   = (const float*)d_in[0];
    const float* h   = (const float*)d_in[1];
    const int*   src = (const int*)  d_in[2];
    const int*   dst = (const int*)  d_in[3];
    const float* Wg  = (const float*)d_in[4];
    const float* bg  = (const float*)d_in[5];
    const float* Wc  = (const float*)d_in[6];
    const float* bc  = (const float*)d_in[7];
    float* out = (float*)d_out;

    int n = in_sizes[0] / 64;
    int E = in_sizes[2];
    int NB = (n + 1023) / 1024;

    cudaFuncSetAttribute(k_gemm1_bucket, cudaFuncAttributeMaxDynamicSharedMemorySize, G1_SMEM_BYTES);
    cudaFuncSetAttribute(k_gemm2,        cudaFuncAttributeMaxDynamicSharedMemorySize, G2_SMEM_BYTES);

    int nb;
    nb = (n + 255) / 256;              k_zero   <<<nb, 256>>>(n);
    nb = (E + 255) / 256;              k_degree <<<nb, 256>>>(src, dst, E);

    k_scan<<<NB, 1024>>>(n);

    int tiles = (n + 127) / 128;
    int bucketB = (E + 255) / 256;
    k_gemm1_bucket<<<tiles + bucketB, 256, G1_SMEM_BYTES>>>(x, h, Wg, src, dst, n, E, tiles);

    nb = (int)(((long long)n * 32 + 255) / 256);
    k_agg1_gates<<<nb, 256>>>(h, bg, n);

    k_gemm2<<<tiles, 256, G2_SMEM_BYTES>>>(x, Wc, n);

    nb = (int)(((long long)n * 16 + 255) / 256);
    k_agg2_final<<<nb, 256>>>(h, bc, out, n);
}

// round 13
// speedup vs baseline: 2.7254x; 1.0089x over previous
#include <cuda_runtime.h>
#include <cuda_fp16.h>
#include <math.h>
#include <stdint.h>

#define NMAX 100000
#define EMAX 2000000

// Scratch (allocation-free rule: __device__ globals)
__device__ int    g_deg_in [NMAX];
__device__ int    g_deg_out[NMAX];
__device__ float  g_s_out[NMAX];
__device__ float  g_s_in [NMAX];
__device__ int    g_row   [NMAX + 1];
__device__ int    g_cursor[NMAX];
__device__ int    g_esrc  [EMAX];
__device__ int    g_blk_agg [128];
__device__ int    g_blk_flag[128];
__device__ int    g_sync;
__device__ __half g_xw1h[(size_t)NMAX * 128];
__device__ __half g_xw2h[(size_t)NMAX * 64];
__device__ float  g_z   [(size_t)NMAX * 64];
__device__ float  g_rh  [(size_t)NMAX * 64];

// ---------------------------------------------------------------------------
__global__ void k_zero(int n) {
    int i = blockIdx.x * blockDim.x + threadIdx.x;
    if (i < n) { g_deg_in[i] = 0; g_deg_out[i] = 0; }
    if (i < 128) g_blk_flag[i] = 0;
    if (i == 128) g_sync = 0;
}

// ---------------------------------------------------------------------------
// HMMA helper
// ---------------------------------------------------------------------------
__device__ __forceinline__ void mma16816(float* c, const uint32_t* a,
                                         uint32_t b0, uint32_t b1) {
    asm volatile(
        "mma.sync.aligned.m16n8k16.row.col.f32.f16.f16.f32 "
        "{%0,%1,%2,%3}, {%4,%5,%6,%7}, {%8,%9}, {%0,%1,%2,%3};\n"
        : "+f"(c[0]), "+f"(c[1]), "+f"(c[2]), "+f"(c[3])
        : "r"(a[0]), "r"(a[1]), "r"(a[2]), "r"(a[3]), "r"(b0), "r"(b1));
}

// ---------------------------------------------------------------------------
// Fused: degree-count (independent edge pass) + UNSCALED GEMM1.
// Blocks [0, tiles): xw1u[N,128] = [x|h] @ Wg  (fp16 out, no s_out)
// Blocks [tiles, ...): degree atomics, 4 edges/thread
// ---------------------------------------------------------------------------
#define G1_SMEM_BYTES ((128*136 + 128*136) * 2)

__global__ __launch_bounds__(256) void k_deg_gemm1(
    const float* __restrict__ x, const float* __restrict__ h,
    const float* __restrict__ Wg,
    const int* __restrict__ src, const int* __restrict__ dst,
    int n, int E, int tiles)
{
    if (blockIdx.x >= tiles) {
        // ---- degree part: 4 edges per thread ----
        int base = ((blockIdx.x - tiles) * 256 + threadIdx.x) * 4;
        if (base + 4 <= E) {
            int4 s4 = *(const int4*)(src + base);
            int4 d4 = *(const int4*)(dst + base);
            atomicAdd(&g_deg_out[s4.x], 1); atomicAdd(&g_deg_in[d4.x], 1);
            atomicAdd(&g_deg_out[s4.y], 1); atomicAdd(&g_deg_in[d4.y], 1);
            atomicAdd(&g_deg_out[s4.z], 1); atomicAdd(&g_deg_in[d4.z], 1);
            atomicAdd(&g_deg_out[s4.w], 1); atomicAdd(&g_deg_in[d4.w], 1);
        } else {
            for (int e = base; e < E; e++) {
                atomicAdd(&g_deg_out[src[e]], 1);
                atomicAdd(&g_deg_in [dst[e]], 1);
            }
        }
        return;
    }

    // ---- GEMM part (unscaled) ----
    extern __shared__ __half sh[];
    __half* Ash = sh;                 // [128][136]
    __half* Wsh = sh + 128 * 136;     // [128][136]  (row = n, col = k)
    int t = threadIdx.x;
    int row0 = blockIdx.x * 128;

    for (int it = t; it < 128 * 32; it += 256) {
        int m = it >> 5, q = it & 31;
        int gr = row0 + m;
        float4 v = make_float4(0.f, 0.f, 0.f, 0.f);
        if (gr < n) {
            const float* srcp = (q < 16) ? (x + (size_t)gr * 64 + q * 4)
                                         : (h + (size_t)gr * 64 + (q - 16) * 4);
            v = *(const float4*)srcp;
        }
        __half2 p0 = __floats2half2_rn(v.x, v.y);
        __half2 p1 = __floats2half2_rn(v.z, v.w);
        *(uint2*)(Ash + m * 136 + q * 4) = make_uint2(*(unsigned*)&p0, *(unsigned*)&p1);
    }
    for (int it = t; it < 128 * 32; it += 256) {
        int k = it >> 5, q = it & 31;
        float4 v = *(const float4*)(Wg + (size_t)k * 128 + q * 4);
        Wsh[(q * 4 + 0) * 136 + k] = __float2half(v.x);
        Wsh[(q * 4 + 1) * 136 + k] = __float2half(v.y);
        Wsh[(q * 4 + 2) * 136 + k] = __float2half(v.z);
        Wsh[(q * 4 + 3) * 136 + k] = __float2half(v.w);
    }
    __syncthreads();

    int wid = t >> 5, lane = t & 31;
    int gp = lane >> 2, tg = lane & 3;
    int wm = (wid >> 1) * 32, wn = (wid & 1) * 64;

    float acc[2][8][4];
#pragma unroll
    for (int mi = 0; mi < 2; mi++)
#pragma unroll
        for (int ni = 0; ni < 8; ni++)
#pragma unroll
            for (int j = 0; j < 4; j++) acc[mi][ni][j] = 0.f;

#pragma unroll
    for (int k0 = 0; k0 < 128; k0 += 16) {
        uint32_t a[2][4];
#pragma unroll
        for (int mi = 0; mi < 2; mi++) {
            int r = wm + mi * 16 + gp;
            a[mi][0] = *(uint32_t*)(Ash + r * 136 + k0 + tg * 2);
            a[mi][1] = *(uint32_t*)(Ash + (r + 8) * 136 + k0 + tg * 2);
            a[mi][2] = *(uint32_t*)(Ash + r * 136 + k0 + 8 + tg * 2);
            a[mi][3] = *(uint32_t*)(Ash + (r + 8) * 136 + k0 + 8 + tg * 2);
        }
#pragma unroll
        for (int ni = 0; ni < 8; ni++) {
            int c = wn + ni * 8 + gp;
            uint32_t b0 = *(uint32_t*)(Wsh + c * 136 + k0 + tg * 2);
            uint32_t b1 = *(uint32_t*)(Wsh + c * 136 + k0 + 8 + tg * 2);
            mma16816(acc[0][ni], a[0], b0, b1);
            mma16816(acc[1][ni], a[1], b0, b1);
        }
    }

#pragma unroll
    for (int mi = 0; mi < 2; mi++) {
        int r = row0 + wm + mi * 16 + gp;
#pragma unroll
        for (int ni = 0; ni < 8; ni++) {
            int c = wn + ni * 8 + tg * 2;
            if (r < n) {
                __half2 p = __floats2half2_rn(acc[mi][ni][0], acc[mi][ni][1]);
                *(unsigned*)(g_xw1h + (size_t)r * 128 + c) = *(unsigned*)&p;
            }
            if (r + 8 < n) {
                __half2 p = __floats2half2_rn(acc[mi][ni][2], acc[mi][ni][3]);
                *(unsigned*)(g_xw1h + (size_t)(r + 8) * 128 + c) = *(unsigned*)&p;
            }
        }
    }
}

// ---------------------------------------------------------------------------
// Single-pass scan (decoupled lookback) + global barrier + bucket scatter.
// <=98 blocks of 1024 threads — all co-resident, so spins are safe.
// ---------------------------------------------------------------------------
__global__ __launch_bounds__(1024) void k_scan_bucket(
    const int* __restrict__ src, const int* __restrict__ dst, int n, int E)
{
    int b = blockIdx.x, t = threadIdx.x;
    int i = b * 1024 + t;
    int v = (i < n) ? g_deg_in[i] : 0;
    int lane = t & 31, wid = t >> 5;

    // block-wide inclusive scan
    int inc = v;
    for (int o = 1; o < 32; o <<= 1) {
        int u = __shfl_up_sync(~0u, inc, o);
        if (lane >= o) inc += u;
    }
    __shared__ int ws[32];
    if (lane == 31) ws[wid] = inc;
    __syncthreads();
    if (t < 32) {
        int u = ws[t];
        for (int o = 1; o < 32; o <<= 1) {
            int w = __shfl_up_sync(~0u, u, o);
            if (t >= o) u += w;
        }
        ws[t] = u;
    }
    __syncthreads();
    int block_incl = inc + (wid ? ws[wid - 1] : 0);
    int total = ws[31];

    if (t == 0) {
        g_blk_agg[b] = total;
        __threadfence();
        *((volatile int*)&g_blk_flag[b]) = 1;
    }

    __shared__ int s_prefix;
    if (wid == 0) {
        int sum = 0;
        for (int p = lane; p < b; p += 32) {
            while (*((volatile int*)&g_blk_flag[p]) == 0) { }
            sum += *((volatile int*)&g_blk_agg[p]);
        }
        for (int o = 16; o > 0; o >>= 1) sum += __shfl_down_sync(~0u, sum, o);
        if (lane == 0) s_prefix = sum;
    }
    __syncthreads();

    int excl = s_prefix + block_incl - v;
    if (i < n) {
        g_row[i]    = excl;
        g_cursor[i] = excl;
        g_s_in [i]  = rsqrtf(fmaxf((float)v, 1.f));
        g_s_out[i]  = rsqrtf(fmaxf((float)g_deg_out[i], 1.f));
        if (i == n - 1) g_row[n] = excl + v;
    }

    // ---- global barrier (all blocks co-resident) ----
    __syncthreads();
    if (t == 0) {
        __threadfence();
        atomicAdd(&g_sync, 1);
        while (*((volatile int*)&g_sync) < gridDim.x) { }
    }
    __syncthreads();
    __threadfence();

    // ---- bucket scatter, grid-stride ----
    int stride = gridDim.x * 1024;
    for (int e = b * 1024 + t; e < E; e += stride) {
        int p = atomicAdd(&g_cursor[dst[e]], 1);
        g_esrc[p] = src[e];
    }
}

// ---------------------------------------------------------------------------
// Agg1 + gates fused: warp per node; s_out applied at gather.
// ---------------------------------------------------------------------------
__global__ __launch_bounds__(256) void k_agg1_gates(
    const float* __restrict__ h, const float* __restrict__ bg, int n)
{
    int gt = blockIdx.x * blockDim.x + threadIdx.x;
    int i = gt >> 5;
    if (i >= n) return;
    int lane = gt & 31;

    int p   = g_row[i];
    int end = g_row[i + 1];
    float4 acc = make_float4(0.f, 0.f, 0.f, 0.f);

    for (; p + 8 <= end; p += 8) {
        int s[8];
#pragma unroll
        for (int j = 0; j < 8; j++) s[j] = __ldg(g_esrc + p + j);
        float so[8];
#pragma unroll
        for (int j = 0; j < 8; j++) so[j] = __ldg(g_s_out + s[j]);
        uint2 u[8];
#pragma unroll
        for (int j = 0; j < 8; j++)
            u[j] = __ldg((const uint2*)(g_xw1h + (size_t)s[j] * 128) + lane);
#pragma unroll
        for (int j = 0; j < 8; j++) {
            float2 a = __half22float2(*(__half2*)&u[j].x);
            float2 b = __half22float2(*(__half2*)&u[j].y);
            acc.x += so[j] * a.x; acc.y += so[j] * a.y;
            acc.z += so[j] * b.x; acc.w += so[j] * b.y;
        }
    }
    if (p + 4 <= end) {
        int s[4];
#pragma unroll
        for (int j = 0; j < 4; j++) s[j] = __ldg(g_esrc + p + j);
        float so[4];
#pragma unroll
        for (int j = 0; j < 4; j++) so[j] = __ldg(g_s_out + s[j]);
        uint2 u[4];
#pragma unroll
        for (int j = 0; j < 4; j++)
            u[j] = __ldg((const uint2*)(g_xw1h + (size_t)s[j] * 128) + lane);
#pragma unroll
        for (int j = 0; j < 4; j++) {
            float2 a = __half22float2(*(__half2*)&u[j].x);
            float2 b = __half22float2(*(__half2*)&u[j].y);
            acc.x += so[j] * a.x; acc.y += so[j] * a.y;
            acc.z += so[j] * b.x; acc.w += so[j] * b.y;
        }
        p += 4;
    }
    for (; p < end; p++) {
        int s0 = __ldg(g_esrc + p);
        float so = __ldg(g_s_out + s0);
        uint2 u0 = __ldg((const uint2*)(g_xw1h + (size_t)s0 * 128) + lane);
        float2 a0 = __half22float2(*(__half2*)&u0.x), b0 = __half22float2(*(__half2*)&u0.y);
        acc.x += so * a0.x; acc.y += so * a0.y;
        acc.z += so * b0.x; acc.w += so * b0.y;
    }

    float si = g_s_in[i];
    float4 b4 = __ldg((const float4*)bg + lane);
    float4 g;
    g.x = 1.f / (1.f + expf(-(acc.x * si + b4.x)));
    g.y = 1.f / (1.f + expf(-(acc.y * si + b4.y)));
    g.z = 1.f / (1.f + expf(-(acc.z * si + b4.z)));
    g.w = 1.f / (1.f + expf(-(acc.w * si + b4.w)));

    if (lane < 16) {
        float4 h4 = __ldg((const float4*)(h + (size_t)i * 64) + lane);
        *((float4*)(g_rh + (size_t)i * 64) + lane) =
            make_float4(g.x * h4.x, g.y * h4.y, g.z * h4.z, g.w * h4.w);
    } else {
        *((float4*)(g_z + (size_t)i * 64) + (lane - 16)) = g;
    }
}

// ---------------------------------------------------------------------------
// GEMM2 (HMMA, unscaled): xw2u[N,64] = [x|rh] @ Wc[128,64]  (fp16 out)
// ---------------------------------------------------------------------------
#define G2_SMEM_BYTES ((128*136 + 64*136) * 2)

__global__ __launch_bounds__(256) void k_gemm2(
    const float* __restrict__ x, const float* __restrict__ Wc, int n)
{
    extern __shared__ __half sh[];
    __half* Ash = sh;               // [128][136]
    __half* Wsh = sh + 128 * 136;   // [64][136]
    int t = threadIdx.x;
    int row0 = blockIdx.x * 128;

    for (int it = t; it < 128 * 32; it += 256) {
        int m = it >> 5, q = it & 31;
        int gr = row0 + m;
        float4 v = make_float4(0.f, 0.f, 0.f, 0.f);
        if (gr < n) {
            const float* srcp = (q < 16) ? (x + (size_t)gr * 64 + q * 4)
                                         : (g_rh + (size_t)gr * 64 + (q - 16) * 4);
            v = *(const float4*)srcp;
        }
        __half2 p0 = __floats2half2_rn(v.x, v.y);
        __half2 p1 = __floats2half2_rn(v.z, v.w);
        *(uint2*)(Ash + m * 136 + q * 4) = make_uint2(*(unsigned*)&p0, *(unsigned*)&p1);
    }
    for (int it = t; it < 128 * 16; it += 256) {
        int k = it >> 4, q = it & 15;
        float4 v = *(const float4*)(Wc + (size_t)k * 64 + q * 4);
        Wsh[(q * 4 + 0) * 136 + k] = __float2half(v.x);
        Wsh[(q * 4 + 1) * 136 + k] = __float2half(v.y);
        Wsh[(q * 4 + 2) * 136 + k] = __float2half(v.z);
        Wsh[(q * 4 + 3) * 136 + k] = __float2half(v.w);
    }
    __syncthreads();

    int wid = t >> 5, lane = t & 31;
    int gp = lane >> 2, tg = lane & 3;
    int wm = wid * 16;

    float acc[8][4];
#pragma unroll
    for (int ni = 0; ni < 8; ni++)
#pragma unroll
        for (int j = 0; j < 4; j++) acc[ni][j] = 0.f;

#pragma unroll
    for (int k0 = 0; k0 < 128; k0 += 16) {
        uint32_t a[4];
        int r = wm + gp;
        a[0] = *(uint32_t*)(Ash + r * 136 + k0 + tg * 2);
        a[1] = *(uint32_t*)(Ash + (r + 8) * 136 + k0 + tg * 2);
        a[2] = *(uint32_t*)(Ash + r * 136 + k0 + 8 + tg * 2);
        a[3] = *(uint32_t*)(Ash + (r + 8) * 136 + k0 + 8 + tg * 2);
#pragma unroll
        for (int ni = 0; ni < 8; ni++) {
            int c = ni * 8 + gp;
            uint32_t b0 = *(uint32_t*)(Wsh + c * 136 + k0 + tg * 2);
            uint32_t b1 = *(uint32_t*)(Wsh + c * 136 + k0 + 8 + tg * 2);
            mma16816(acc[ni], a, b0, b1);
        }
    }

    int r = row0 + wm + gp;
#pragma unroll
    for (int ni = 0; ni < 8; ni++) {
        int c = ni * 8 + tg * 2;
        if (r < n) {
            __half2 p = __floats2half2_rn(acc[ni][0], acc[ni][1]);
            *(unsigned*)(g_xw2h + (size_t)r * 64 + c) = *(unsigned*)&p;
        }
        if (r + 8 < n) {
            __half2 p = __floats2half2_rn(acc[ni][2], acc[ni][3]);
            *(unsigned*)(g_xw2h + (size_t)(r + 8) * 64 + c) = *(unsigned*)&p;
        }
    }
}

// ---------------------------------------------------------------------------
// Agg2 + GRU epilogue fused: 16 lanes per node; s_out applied at gather.
// ---------------------------------------------------------------------------
__global__ __launch_bounds__(256) void k_agg2_final(
    const float* __restrict__ h, const float* __restrict__ bc,
    float* __restrict__ out, int n)
{
    int gt = blockIdx.x * blockDim.x + threadIdx.x;
    int i = gt >> 4;
    if (i >= n) return;
    int q = gt & 15;

    int p   = g_row[i];
    int end = g_row[i + 1];
    float4 acc = make_float4(0.f, 0.f, 0.f, 0.f);

    for (; p + 8 <= end; p += 8) {
        int s[8];
#pragma unroll
        for (int j = 0; j < 8; j++) s[j] = __ldg(g_esrc + p + j);
        float so[8];
#pragma unroll
        for (int j = 0; j < 8; j++) so[j] = __ldg(g_s_out + s[j]);
        uint2 u[8];
#pragma unroll
        for (int j = 0; j < 8; j++)
            u[j] = __ldg((const uint2*)(g_xw2h + (size_t)s[j] * 64) + q);
#pragma unroll
        for (int j = 0; j < 8; j++) {
            float2 a = __half22float2(*(__half2*)&u[j].x);
            float2 b = __half22float2(*(__half2*)&u[j].y);
            acc.x += so[j] * a.x; acc.y += so[j] * a.y;
            acc.z += so[j] * b.x; acc.w += so[j] * b.y;
        }
    }
    if (p + 4 <= end) {
        int s[4];
#pragma unroll
        for (int j = 0; j < 4; j++) s[j] = __ldg(g_esrc + p + j);
        float so[4];
#pragma unroll
        for (int j = 0; j < 4; j++) so[j] = __ldg(g_s_out + s[j]);
        uint2 u[4];
#pragma unroll
        for (int j = 0; j < 4; j++)
            u[j] = __ldg((const uint2*)(g_xw2h + (size_t)s[j] * 64) + q);
#pragma unroll
        for (int j = 0; j < 4; j++) {
            float2 a = __half22float2(*(__half2*)&u[j].x);
            float2 b = __half22float2(*(__half2*)&u[j].y);
            acc.x += so[j] * a.x; acc.y += so[j] * a.y;
            acc.z += so[j] * b.x; acc.w += so[j] * b.y;
        }
        p += 4;
    }
    for (; p < end; p++) {
        int s0 = __ldg(g_esrc + p);
        float so = __ldg(g_s_out + s0);
        uint2 u0 = __ldg((const uint2*)(g_xw2h + (size_t)s0 * 64) + q);
        float2 a0 = __half22float2(*(__half2*)&u0.x), b0 = __half22float2(*(__half2*)&u0.y);
        acc.x += so * a0.x; acc.y += so * a0.y;
        acc.z += so * b0.x; acc.w += so * b0.y;
    }

    float si = g_s_in[i];
    float4 b4 = __ldg((const float4*)bc + q);
    float4 z4 = *((const float4*)(g_z + (size_t)i * 64) + q);
    float4 h4 = __ldg((const float4*)(h + (size_t)i * 64) + q);
    float4 o;
    o.x = z4.x * h4.x + (1.f - z4.x) * tanhf(acc.x * si + b4.x);
    o.y = z4.y * h4.y + (1.f - z4.y) * tanhf(acc.y * si + b4.y);
    o.z = z4.z * h4.z + (1.f - z4.z) * tanhf(acc.z * si + b4.z);
    o.w = z4.w * h4.w + (1.f - z4.w) * tanhf(acc.w * si + b4.w);
    *((float4*)(out + (size_t)i * 64) + q) = o;
}

// ---------------------------------------------------------------------------
extern "C" void kernel_launch(void* const* d_in, const int* in_sizes, int n_in,
                              void* d_out, int out_size)
{
    const float* x   = (const float*)d_in[0];
    const float* h   = (const float*)d_in[1];
    const int*   src = (const int*)  d_in[2];
    const int*   dst = (const int*)  d_in[3];
    const float* Wg  = (const float*)d_in[4];
    const float* bg  = (const float*)d_in[5];
    const float* Wc  = (const float*)d_in[6];
    const float* bc  = (const float*)d_in[7];
    float* out = (float*)d_out;

    int n = in_sizes[0] / 64;
    int E = in_sizes[2];
    int NB = (n + 1023) / 1024;

    cudaFuncSetAttribute(k_deg_gemm1, cudaFuncAttributeMaxDynamicSharedMemorySize, G1_SMEM_BYTES);
    cudaFuncSetAttribute(k_gemm2,     cudaFuncAttributeMaxDynamicSharedMemorySize, G2_SMEM_BYTES);

    int nb;
    nb = (n + 255) / 256;
    k_zero<<<nb, 256>>>(n);

    int tiles = (n + 127) / 128;
    int degB = (E + 1023) / 1024;   // 4 edges/thread, 256 threads
    k_deg_gemm1<<<tiles + degB, 256, G1_SMEM_BYTES>>>(x, h, Wg, src, dst, n, E, tiles);

    k_scan_bucket<<<NB, 1024>>>(src, dst, n, E);

    nb = (int)(((long long)n * 32 + 255) / 256);
    k_agg1_gates<<<nb, 256>>>(h, bg, n);

    k_gemm2<<<tiles, 256, G2_SMEM_BYTES>>>(x, Wc, n);

    nb = (int)(((long long)n * 16 + 255) / 256);
    k_agg2_final<<<nb, 256>>>(h, bc, out, n);
}